// round 1
// baseline (speedup 1.0000x reference)
#include <cuda_runtime.h>

// Problem constants
#define B_  64
#define T_  512
#define D_  128
#define H_  512
#define O_  256

#define NCTA 128          // CTAs in persistent kernel
#define JPC  4            // hidden units per CTA  (H_/NCTA)
#define NTHR 256          // threads per CTA (64 batch x 4 j_local)

// ---------------- device scratch (static: no allocations allowed) ----------
__device__ float    g_h[2][H_ * B_];        // double-buffered hidden state [buf][j*B + b]
__device__ float    g_hs[T_ * H_ * B_];     // all hidden states [t][j][b]  (64 MB)
__device__ float    g_xT[T_ * D_ * B_];     // transposed input  [t][d][b]  (16 MB)
__device__ unsigned g_bar_cnt;              // grid barrier state (returns to 0 each barrier)
__device__ unsigned g_bar_gen;              // generation counter (monotonic; compared relatively)

// ---------------- prep: transpose x and h0 into [.. , b]-fastest layouts ---
__global__ void prep_kernel(const float* __restrict__ x, const float* __restrict__ h0)
{
    int stride = gridDim.x * blockDim.x;
    int tid0 = blockIdx.x * blockDim.x + threadIdx.x;
    // xT[(t*D+d)*B + b] = x[(b*T+t)*D + d]
    for (int i = tid0; i < T_ * D_ * B_; i += stride) {
        int b = i & (B_ - 1);
        int d = (i / B_) & (D_ - 1);
        int t = i / (B_ * D_);
        g_xT[i] = x[(b * T_ + t) * D_ + d];
    }
    // g_h[0][j*B + b] = h0[b*H + j]
    for (int i = tid0; i < H_ * B_; i += stride) {
        int b = i & (B_ - 1);
        int j = i / B_;
        g_h[0][i] = h0[b * H_ + j];
    }
}

// ---------------- persistent recurrent kernel ------------------------------
// Shared layout:
//   h_s  [H][B]   : 131072 B   (hidden state, [k][b] -> conflict-free across b)
//   x_s  [D][B]   :  32768 B   (x_t, [d][b])
//   Us4  [H][JPC] :  32768 B   (float4 = 4 gates interleaved; warp-uniform broadcast)
//   Ws4  [D][JPC] :   8192 B
// total 204800 B dynamic shared -> 1 CTA/SM, 128 CTAs all resident (148 SMs).
#define SMEM_BYTES ((H_*B_ + D_*B_ + H_*JPC*4 + D_*JPC*4) * 4)

__device__ __forceinline__ float sigmoid_f(float x) {
    return 1.0f / (1.0f + __expf(-x));
}

__global__ void __launch_bounds__(NTHR, 1) lstm_kernel(
    const float* __restrict__ U,    // [H][4H]
    const float* __restrict__ W,    // [D][4H]
    const float* __restrict__ bias, // [4H]
    const float* __restrict__ c0)   // [B][H]
{
    extern __shared__ float smem[];
    float*  h_s  = smem;                          // H*B
    float*  x_s  = h_s + H_ * B_;                 // D*B
    float4* Us4  = (float4*)(x_s + D_ * B_);      // H*JPC float4
    float4* Ws4  = Us4 + H_ * JPC;                // D*JPC float4

    const int tid   = threadIdx.x;
    const int b     = tid & (B_ - 1);             // 0..63
    const int jl    = tid >> 6;                   // 0..3
    const int jglob = blockIdx.x * JPC + jl;

    // One-time load of this CTA's recurrent/input weight slices (reused 512 steps).
    for (int i = tid; i < H_ * JPC; i += NTHR) {
        int k = i >> 2, j = i & 3;
        int col = blockIdx.x * JPC + j;
        const float* row = U + k * (4 * H_);
        Us4[(k << 2) + j] = make_float4(row[col], row[H_ + col],
                                        row[2 * H_ + col], row[3 * H_ + col]);
    }
    for (int i = tid; i < D_ * JPC; i += NTHR) {
        int d = i >> 2, j = i & 3;
        int col = blockIdx.x * JPC + j;
        const float* row = W + d * (4 * H_);
        Ws4[(d << 2) + j] = make_float4(row[col], row[H_ + col],
                                        row[2 * H_ + col], row[3 * H_ + col]);
    }
    const float bi  = bias[jglob];
    const float bf  = bias[H_ + jglob];
    const float bg  = bias[2 * H_ + jglob];
    const float bo_ = bias[3 * H_ + jglob];
    float c = c0[b * H_ + jglob];                 // cell state lives in a register
    __syncthreads();

    for (int t = 0; t < T_; ++t) {
        // Stage h (L1-bypassing: written by other SMs) and x_t into shared.
        {
            const float4* hsrc4 = (const float4*)g_h[t & 1];
            float4* h_s4 = (float4*)h_s;
            #pragma unroll 4
            for (int i = tid; i < (H_ * B_) / 4; i += NTHR)
                h_s4[i] = __ldcg(hsrc4 + i);
            const float4* xsrc4 = (const float4*)(g_xT + t * D_ * B_);
            float4* x_s4 = (float4*)x_s;
            #pragma unroll 4
            for (int i = tid; i < (D_ * B_) / 4; i += NTHR)
                x_s4[i] = xsrc4[i];
        }
        __syncthreads();

        float a0 = bi, a1 = bf, a2 = bg, a3 = bo_;
        #pragma unroll 8
        for (int k = 0; k < H_; ++k) {
            float  hv = h_s[k * B_ + b];
            float4 u  = Us4[(k << 2) + jl];       // warp-uniform -> broadcast
            a0 = fmaf(hv, u.x, a0);
            a1 = fmaf(hv, u.y, a1);
            a2 = fmaf(hv, u.z, a2);
            a3 = fmaf(hv, u.w, a3);
        }
        #pragma unroll 8
        for (int d = 0; d < D_; ++d) {
            float  xv = x_s[d * B_ + b];
            float4 w  = Ws4[(d << 2) + jl];
            a0 = fmaf(xv, w.x, a0);
            a1 = fmaf(xv, w.y, a1);
            a2 = fmaf(xv, w.z, a2);
            a3 = fmaf(xv, w.w, a3);
        }

        float ig = sigmoid_f(a0);
        float fg = sigmoid_f(a1);
        float gg = tanhf(a2);
        float og = sigmoid_f(a3);
        c = fg * c + ig * gg;
        float hn = og * tanhf(c);

        __stcg(&g_h[(t + 1) & 1][jglob * B_ + b], hn);
        g_hs[(t * H_ + jglob) * B_ + b] = hn;

        // ---- grid barrier (one per step; h double-buffered) ----
        __syncthreads();
        if (tid == 0) {
            __threadfence();
            unsigned gen = *(volatile unsigned*)&g_bar_gen;
            unsigned arr = atomicAdd(&g_bar_cnt, 1u);
            if (arr == NCTA - 1) {
                g_bar_cnt = 0;
                __threadfence();
                atomicAdd(&g_bar_gen, 1u);
            } else {
                while (*(volatile unsigned*)&g_bar_gen == gen) { }
            }
            __threadfence();
        }
        __syncthreads();
    }
}

// ---------------- output projection: out[b,t,o] = hs[t,:,b] . Wo[:,o] + bo --
__global__ void __launch_bounds__(256) proj_kernel(
    const float* __restrict__ Wo,   // [H][O]
    const float* __restrict__ bo,   // [O]
    float* __restrict__ out)        // [B][T][O]
{
    __shared__ float4 a_s[64 * 16]; // [jj][b/4]
    __shared__ float4 w_s[64 * 16]; // [jj][o/4]
    const int t   = blockIdx.x;
    const int ot  = blockIdx.y;     // o-tile of 64
    const int tid = threadIdx.x;
    const int tb  = tid & 15;       // b0 = tb*4
    const int to  = tid >> 4;       // o0 = ot*64 + to*4

    float acc[4][4];
    #pragma unroll
    for (int r = 0; r < 4; ++r)
        #pragma unroll
        for (int cc = 0; cc < 4; ++cc) acc[r][cc] = 0.0f;

    for (int jc = 0; jc < H_ / 64; ++jc) {
        const float4* asrc = (const float4*)(g_hs + (t * H_ + jc * 64) * B_);
        #pragma unroll
        for (int i = tid; i < 64 * 16; i += 256) a_s[i] = asrc[i];
        #pragma unroll
        for (int i = tid; i < 64 * 16; i += 256) {
            int jj = i >> 4, o4 = i & 15;
            w_s[i] = *(const float4*)(Wo + (jc * 64 + jj) * O_ + ot * 64 + o4 * 4);
        }
        __syncthreads();
        #pragma unroll 8
        for (int jj = 0; jj < 64; ++jj) {
            float4 av = a_s[jj * 16 + tb];
            float4 wv = w_s[jj * 16 + to];
            acc[0][0] = fmaf(av.x, wv.x, acc[0][0]);
            acc[0][1] = fmaf(av.x, wv.y, acc[0][1]);
            acc[0][2] = fmaf(av.x, wv.z, acc[0][2]);
            acc[0][3] = fmaf(av.x, wv.w, acc[0][3]);
            acc[1][0] = fmaf(av.y, wv.x, acc[1][0]);
            acc[1][1] = fmaf(av.y, wv.y, acc[1][1]);
            acc[1][2] = fmaf(av.y, wv.z, acc[1][2]);
            acc[1][3] = fmaf(av.y, wv.w, acc[1][3]);
            acc[2][0] = fmaf(av.z, wv.x, acc[2][0]);
            acc[2][1] = fmaf(av.z, wv.y, acc[2][1]);
            acc[2][2] = fmaf(av.z, wv.z, acc[2][2]);
            acc[2][3] = fmaf(av.z, wv.w, acc[2][3]);
            acc[3][0] = fmaf(av.w, wv.x, acc[3][0]);
            acc[3][1] = fmaf(av.w, wv.y, acc[3][1]);
            acc[3][2] = fmaf(av.w, wv.z, acc[3][2]);
            acc[3][3] = fmaf(av.w, wv.w, acc[3][3]);
        }
        __syncthreads();
    }

    const int obase = ot * 64 + to * 4;
    float4 bv = *(const float4*)(bo + obase);
    #pragma unroll
    for (int r = 0; r < 4; ++r) {
        int bb = tb * 4 + r;
        float4 v = make_float4(acc[r][0] + bv.x, acc[r][1] + bv.y,
                               acc[r][2] + bv.z, acc[r][3] + bv.w);
        *(float4*)(out + (bb * T_ + t) * O_ + obase) = v;
    }
}

// ---------------- launch --------------------------------------------------
extern "C" void kernel_launch(void* const* d_in, const int* in_sizes, int n_in,
                              void* d_out, int out_size)
{
    const float* x   = (const float*)d_in[0];
    const float* h0  = (const float*)d_in[1];
    const float* c0  = (const float*)d_in[2];
    const float* W   = (const float*)d_in[3];
    const float* U   = (const float*)d_in[4];
    const float* bia = (const float*)d_in[5];
    const float* Wo  = (const float*)d_in[6];
    const float* bo  = (const float*)d_in[7];
    float* out = (float*)d_out;
    (void)in_sizes; (void)n_in; (void)out_size;

    cudaFuncSetAttribute(lstm_kernel,
                         cudaFuncAttributeMaxDynamicSharedMemorySize, SMEM_BYTES);

    prep_kernel<<<2048, 256>>>(x, h0);
    lstm_kernel<<<NCTA, NTHR, SMEM_BYTES>>>(U, W, bia, c0);
    dim3 pg(T_, O_ / 64);
    proj_kernel<<<pg, 256>>>(Wo, bo, out);
}

// round 3
// speedup vs baseline: 1.7799x; 1.7799x over previous
#include <cuda_runtime.h>
#include <cuda_bf16.h>
#include <cstdint>

// Problem constants
#define B_  64
#define T_  512
#define D_  128
#define H_  512
#define O_  256

#define NCTA 128          // persistent CTAs (1 per SM)
#define NTHR 256          // 8 warps
#define KTOT 640          // K = H (recurrent) + D (input)

// ---------------- device scratch ------------------------------------------
__device__ uint32_t g_hpack[2][B_ * H_];          // packed (bf16 hi | lo<<16), [b][j]
__device__ uint32_t g_xpack[T_ * B_ * D_];        // packed x splits, [t][b][d]
__device__ float    g_hs[T_ * H_ * B_];           // hidden states [t][j][b] for proj
__device__ unsigned g_bar_cnt;
__device__ unsigned g_bar_gen;

// ---------------- PTX helpers ---------------------------------------------
__device__ __forceinline__ uint32_t smem_u32(const void* p) {
    uint32_t a;
    asm("{ .reg .u64 t; cvta.to.shared.u64 t, %1; cvt.u32.u64 %0, t; }" : "=r"(a) : "l"(p));
    return a;
}

#define LDSM_X4(r0, r1, r2, r3, addr) \
    asm volatile("ldmatrix.sync.aligned.m8n8.x4.shared.b16 {%0,%1,%2,%3}, [%4];" \
        : "=r"(r0), "=r"(r1), "=r"(r2), "=r"(r3) : "r"(addr))

#define MMA_BF16(c, a0, a1, a2, a3, b0, b1) \
    asm volatile("mma.sync.aligned.m16n8k16.row.col.f32.bf16.bf16.f32 " \
        "{%0,%1,%2,%3}, {%4,%5,%6,%7}, {%8,%9}, {%0,%1,%2,%3};" \
        : "+f"((c)[0]), "+f"((c)[1]), "+f"((c)[2]), "+f"((c)[3]) \
        : "r"(a0), "r"(a1), "r"(a2), "r"(a3), "r"(b0), "r"(b1))

// ---------------- bf16 hi/lo packing --------------------------------------
__device__ __forceinline__ uint32_t pack_split(float v) {
    __nv_bfloat16 hb = __float2bfloat16(v);
    float hv = __bfloat162float(hb);
    __nv_bfloat16 lb = __float2bfloat16(v - hv);
    return (uint32_t)__bfloat16_as_ushort(hb) | ((uint32_t)__bfloat16_as_ushort(lb) << 16);
}

// ---------------- prep: pack x (transposed) and h0 -------------------------
__global__ void prep_kernel(const float* __restrict__ x, const float* __restrict__ h0)
{
    int stride = gridDim.x * blockDim.x;
    int tid0 = blockIdx.x * blockDim.x + threadIdx.x;
    // g_xpack[t*B*D + b*D + d] = split(x[(b*T+t)*D + d])
    for (int i = tid0; i < T_ * B_ * D_; i += stride) {
        int d = i & (D_ - 1);
        int b = (i >> 7) & (B_ - 1);
        int t = i >> 13;
        g_xpack[i] = pack_split(x[(b * T_ + t) * D_ + d]);
    }
    for (int i = tid0; i < B_ * H_; i += stride)
        g_hpack[0][i] = pack_split(h0[i]);
}

// ---------------- SMEM layout ---------------------------------------------
// A: 128 rows (64 batch-hi + 64 batch-lo) x 640 bf16, row stride 648 bf16 (1296 B)
// B: 32 rows (16 gate-col hi + 16 lo)   x 640 bf16, row stride 1296 B
// padded stride => ldmatrix phases hit 8 distinct 128B lines (conflict-free)
#define ASTRIDE   1296
#define SM_ZHI    0                        // 64*18 floats = 4608 B
#define SM_ZLO    4608
#define SM_A      9216
#define A_BYTES   (128 * ASTRIDE)          // 165888
#define SM_B      (SM_A + A_BYTES)         // 175104
#define B_BYTES   (32 * ASTRIDE)           // 41472
#define SMEM_TOTAL (SM_B + B_BYTES)        // 216576

__device__ __forceinline__ float sigmoid_f(float x) {
    return 1.0f / (1.0f + __expf(-x));
}

__global__ void __launch_bounds__(NTHR, 1)
lstm_kernel(const float* __restrict__ U,    // [H][4H]
            const float* __restrict__ W,    // [D][4H]
            const float* __restrict__ bias, // [4H]
            const float* __restrict__ c0)   // [B][H]
{
    extern __shared__ char smem[];
    const uint32_t smem_base = smem_u32(smem);
    float* zhi_s = (float*)(smem + SM_ZHI);   // [64][18]
    float* zlo_s = (float*)(smem + SM_ZLO);   // [64][18]

    const int tid  = threadIdx.x;
    const int wid  = tid >> 5;
    const int lane = tid & 31;
    const int cta  = blockIdx.x;

    // ---- one-time: build B (weights hi/lo), rows n: n<16 hi, n>=16 lo ----
    // gate column for n' = n&15:  col = (n'&3)*H + cta*4 + (n'>>2)
    for (int np = 0; np < 16; ++np) {
        int col = (np & 3) * H_ + cta * 4 + (np >> 2);
        for (int k = tid; k < KTOT; k += NTHR) {
            float v = (k < H_) ? U[k * (4 * H_) + col] : W[(k - H_) * (4 * H_) + col];
            __nv_bfloat16 hb = __float2bfloat16(v);
            __nv_bfloat16 lb = __float2bfloat16(v - __bfloat162float(hb));
            *(uint16_t*)(smem + SM_B + np * ASTRIDE + k * 2) = __bfloat16_as_ushort(hb);
            *(uint16_t*)(smem + SM_B + (np + 16) * ASTRIDE + k * 2) = __bfloat16_as_ushort(lb);
        }
    }

    // ---- per-lane persistent state (warps 0,1: lane index = batch b) ----
    float c_st[4];
    float bias_r[16];
    if (wid < 2) {
        int b = wid * 32 + lane;
        #pragma unroll
        for (int jl = 0; jl < 4; ++jl)
            c_st[jl] = c0[b * H_ + cta * 4 + jl];
        #pragma unroll
        for (int n = 0; n < 16; ++n)
            bias_r[n] = bias[(n & 3) * H_ + cta * 4 + (n >> 2)];
    }

    // ---- precompute ldmatrix lane addresses (k-offset added per step) ----
    // A frag x4 matrices: (m0,k0),(m0+8,k0),(m0,k0+8),(m0+8,k0+8)
    const int m0 = 16 * wid;
    const uint32_t a_addr0 = smem_base + SM_A
        + (uint32_t)(m0 + (lane & 7) + ((lane >> 3) & 1) * 8) * ASTRIDE
        + (uint32_t)((lane >> 4) * 16);
    // B frag x4 matrices for n-tile pair (n0, n0+8): (n0,k0),(n0,k0+8),(n0+8,k0),(n0+8,k0+8)
    const uint32_t b_addr0 = smem_base + SM_B
        + (uint32_t)((lane & 7) + (lane >> 4) * 8) * ASTRIDE
        + (uint32_t)(((lane >> 3) & 1) * 16);

    __syncthreads();

    for (int t = 0; t < T_; ++t) {
        // ---- stage A: warp w stages batch rows w*8..w*8+7 (hi) and +64 (lo) ----
        {
            const int buf = t & 1;
            #pragma unroll
            for (int rr = 0; rr < 8; ++rr) {
                const int b = wid * 8 + rr;
                const uint32_t* hsrc = g_hpack[buf] + b * H_;
                const uint32_t* xsrc = g_xpack + ((size_t)t * B_ + b) * D_;
                char* arow_hi = smem + SM_A + b * ASTRIDE;
                char* arow_lo = arow_hi + 64 * ASTRIDE;
                #pragma unroll
                for (int it = 0; it < 10; ++it) {
                    int j = it * 64 + 2 * lane;
                    uint2 v = (it < 8) ? *(const uint2*)(hsrc + j)
                                       : *(const uint2*)(xsrc + (j - H_));
                    uint32_t hp = __byte_perm(v.x, v.y, 0x5410);
                    uint32_t lp = __byte_perm(v.x, v.y, 0x7632);
                    *(uint32_t*)(arow_hi + j * 2) = hp;
                    *(uint32_t*)(arow_lo + j * 2) = lp;
                }
            }
        }
        __syncthreads();

        // ---- warp MMA: C[16 (m)][32 (n)] per warp, K=640 ----
        float c0r[4], c1r[4], c2r[4], c3r[4];
        #pragma unroll
        for (int i = 0; i < 4; ++i) { c0r[i] = 0.f; c1r[i] = 0.f; c2r[i] = 0.f; c3r[i] = 0.f; }

        #pragma unroll 8
        for (int s = 0; s < KTOT / 16; ++s) {
            const uint32_t koff = (uint32_t)(32 * s);
            uint32_t a0, a1, a2, a3;
            LDSM_X4(a0, a1, a2, a3, a_addr0 + koff);
            uint32_t b0, b1, b2, b3;
            LDSM_X4(b0, b1, b2, b3, b_addr0 + koff);                      // n-tiles 0,1
            uint32_t b4, b5, b6, b7;
            LDSM_X4(b4, b5, b6, b7, b_addr0 + 16u * ASTRIDE + koff);      // n-tiles 2,3
            MMA_BF16(c0r, a0, a1, a2, a3, b0, b1);
            MMA_BF16(c1r, a0, a1, a2, a3, b2, b3);
            MMA_BF16(c2r, a0, a1, a2, a3, b4, b5);
            MMA_BF16(c3r, a0, a1, a2, a3, b6, b7);
        }

        // ---- fold hi/lo B chains: z_part[n] = C[.][n] + C[.][n+16], n=0..15 ----
        // lane holds rows r=lane/4, r+8 ; cols 2*(lane&3)+{0,1} within each n-tile
        {
            float* zarr = (wid < 4) ? zhi_s : zlo_s;
            int brow = (wid & 3) * 16 + (lane >> 2);
            int ccol = 2 * (lane & 3);
            // n-tile 0 + n-tile 2  -> n = ccol
            zarr[brow * 18 + ccol]           = c0r[0] + c2r[0];
            zarr[brow * 18 + ccol + 1]       = c0r[1] + c2r[1];
            zarr[(brow + 8) * 18 + ccol]     = c0r[2] + c2r[2];
            zarr[(brow + 8) * 18 + ccol + 1] = c0r[3] + c2r[3];
            // n-tile 1 + n-tile 3  -> n = 8 + ccol
            zarr[brow * 18 + 8 + ccol]           = c1r[0] + c3r[0];
            zarr[brow * 18 + 8 + ccol + 1]       = c1r[1] + c3r[1];
            zarr[(brow + 8) * 18 + 8 + ccol]     = c1r[2] + c3r[2];
            zarr[(brow + 8) * 18 + 8 + ccol + 1] = c1r[3] + c3r[3];
        }
        __syncthreads();

        // ---- gates (warps 0,1; lane = batch b) ----
        if (wid < 2) {
            int b = wid * 32 + lane;
            float z[16];
            #pragma unroll
            for (int n = 0; n < 16; ++n)
                z[n] = zhi_s[b * 18 + n] + zlo_s[b * 18 + n] + bias_r[n];
            #pragma unroll
            for (int jl = 0; jl < 4; ++jl) {
                float ig = sigmoid_f(z[jl * 4 + 0]);
                float fg = sigmoid_f(z[jl * 4 + 1]);
                float gg = tanhf(z[jl * 4 + 2]);
                float og = sigmoid_f(z[jl * 4 + 3]);
                float cn = fg * c_st[jl] + ig * gg;
                c_st[jl] = cn;
                float hn = og * tanhf(cn);
                int j = cta * 4 + jl;
                g_hs[((size_t)t * H_ + j) * B_ + b] = hn;            // for proj
                g_hpack[(t & 1) ^ 1][b * H_ + j] = pack_split(hn);   // for next step
            }
        }

        // ---- grid barrier ----
        __syncthreads();
        if (tid == 0) {
            __threadfence();
            unsigned gen = *(volatile unsigned*)&g_bar_gen;
            unsigned arr = atomicAdd(&g_bar_cnt, 1u);
            if (arr == NCTA - 1) {
                g_bar_cnt = 0;
                __threadfence();
                atomicAdd(&g_bar_gen, 1u);
            } else {
                while (*(volatile unsigned*)&g_bar_gen == gen) { }
            }
            __threadfence();
        }
        __syncthreads();
    }
}

// ---------------- output projection: out[b,t,o] = hs[t,:,b] . Wo[:,o] + bo --
__global__ void __launch_bounds__(256) proj_kernel(
    const float* __restrict__ Wo,   // [H][O]
    const float* __restrict__ bo,   // [O]
    float* __restrict__ out)        // [B][T][O]
{
    __shared__ float4 a_s[64 * 16];
    __shared__ float4 w_s[64 * 16];
    const int t   = blockIdx.x;
    const int ot  = blockIdx.y;
    const int tid = threadIdx.x;
    const int tb  = tid & 15;
    const int to  = tid >> 4;

    float acc[4][4];
    #pragma unroll
    for (int r = 0; r < 4; ++r)
        #pragma unroll
        for (int cc = 0; cc < 4; ++cc) acc[r][cc] = 0.0f;

    for (int jc = 0; jc < H_ / 64; ++jc) {
        const float4* asrc = (const float4*)(g_hs + ((size_t)t * H_ + jc * 64) * B_);
        #pragma unroll
        for (int i = tid; i < 64 * 16; i += 256) a_s[i] = asrc[i];
        #pragma unroll
        for (int i = tid; i < 64 * 16; i += 256) {
            int jj = i >> 4, o4 = i & 15;
            w_s[i] = *(const float4*)(Wo + (jc * 64 + jj) * O_ + ot * 64 + o4 * 4);
        }
        __syncthreads();
        #pragma unroll 8
        for (int jj = 0; jj < 64; ++jj) {
            float4 av = a_s[jj * 16 + tb];
            float4 wv = w_s[jj * 16 + to];
            acc[0][0] = fmaf(av.x, wv.x, acc[0][0]);
            acc[0][1] = fmaf(av.x, wv.y, acc[0][1]);
            acc[0][2] = fmaf(av.x, wv.z, acc[0][2]);
            acc[0][3] = fmaf(av.x, wv.w, acc[0][3]);
            acc[1][0] = fmaf(av.y, wv.x, acc[1][0]);
            acc[1][1] = fmaf(av.y, wv.y, acc[1][1]);
            acc[1][2] = fmaf(av.y, wv.z, acc[1][2]);
            acc[1][3] = fmaf(av.y, wv.w, acc[1][3]);
            acc[2][0] = fmaf(av.z, wv.x, acc[2][0]);
            acc[2][1] = fmaf(av.z, wv.y, acc[2][1]);
            acc[2][2] = fmaf(av.z, wv.z, acc[2][2]);
            acc[2][3] = fmaf(av.z, wv.w, acc[2][3]);
            acc[3][0] = fmaf(av.w, wv.x, acc[3][0]);
            acc[3][1] = fmaf(av.w, wv.y, acc[3][1]);
            acc[3][2] = fmaf(av.w, wv.z, acc[3][2]);
            acc[3][3] = fmaf(av.w, wv.w, acc[3][3]);
        }
        __syncthreads();
    }

    const int obase = ot * 64 + to * 4;
    float4 bv = *(const float4*)(bo + obase);
    #pragma unroll
    for (int r = 0; r < 4; ++r) {
        int bb = tb * 4 + r;
        float4 v = make_float4(acc[r][0] + bv.x, acc[r][1] + bv.y,
                               acc[r][2] + bv.z, acc[r][3] + bv.w);
        *(float4*)(out + ((size_t)bb * T_ + t) * O_ + obase) = v;
    }
}

// ---------------- launch --------------------------------------------------
extern "C" void kernel_launch(void* const* d_in, const int* in_sizes, int n_in,
                              void* d_out, int out_size)
{
    const float* x   = (const float*)d_in[0];
    const float* h0  = (const float*)d_in[1];
    const float* c0  = (const float*)d_in[2];
    const float* W   = (const float*)d_in[3];
    const float* U   = (const float*)d_in[4];
    const float* bia = (const float*)d_in[5];
    const float* Wo  = (const float*)d_in[6];
    const float* bo  = (const float*)d_in[7];
    float* out = (float*)d_out;
    (void)in_sizes; (void)n_in; (void)out_size;

    cudaFuncSetAttribute(lstm_kernel,
                         cudaFuncAttributeMaxDynamicSharedMemorySize, SMEM_TOTAL);

    prep_kernel<<<1024, 256>>>(x, h0);
    lstm_kernel<<<NCTA, NTHR, SMEM_TOTAL>>>(U, W, bia, c0);
    dim3 pg(T_, O_ / 64);
    proj_kernel<<<pg, 256>>>(Wo, bo, out);
}

// round 4
// speedup vs baseline: 1.8391x; 1.0333x over previous
#include <cuda_runtime.h>
#include <cuda_bf16.h>
#include <cstdint>

// Problem constants
#define B_  64
#define T_  512
#define D_  128
#define H_  512
#define O_  256

#define NCTA 128          // persistent CTAs
#define NTHR 256          // 8 warps
#define KTOT 640          // K = H + D

// ---------------- device scratch ------------------------------------------
__device__ uint16_t g_hhi[2][B_ * H_];     // bf16 hi of h, [buf][b][j]
__device__ uint16_t g_hlo[2][B_ * H_];     // bf16 lo of h
__device__ uint16_t g_xhi[T_ * B_ * D_];   // bf16 hi of x, [t][b][d]
__device__ uint16_t g_xlo[T_ * B_ * D_];
__device__ float    g_hs[T_ * H_ * B_];    // hidden states [t][j][b] for proj
__device__ unsigned g_bar_cnt;
__device__ unsigned g_bar_gen;

// ---------------- PTX helpers ---------------------------------------------
__device__ __forceinline__ uint32_t smem_u32(const void* p) {
    uint32_t a;
    asm("{ .reg .u64 t; cvta.to.shared.u64 t, %1; cvt.u32.u64 %0, t; }" : "=r"(a) : "l"(p));
    return a;
}
__device__ __forceinline__ void cp16(uint32_t s, const void* g) {
    asm volatile("cp.async.cg.shared.global [%0], [%1], 16;" :: "r"(s), "l"(g));
}
#define CP_COMMIT() asm volatile("cp.async.commit_group;" ::: "memory")
#define CP_WAIT0()  asm volatile("cp.async.wait_group 0;" ::: "memory")

#define LDSM_X4(r0, r1, r2, r3, addr) \
    asm volatile("ldmatrix.sync.aligned.m8n8.x4.shared.b16 {%0,%1,%2,%3}, [%4];" \
        : "=r"(r0), "=r"(r1), "=r"(r2), "=r"(r3) : "r"(addr))

#define MMA_BF16(c, a0, a1, a2, a3, b0, b1) \
    asm volatile("mma.sync.aligned.m16n8k16.row.col.f32.bf16.bf16.f32 " \
        "{%0,%1,%2,%3}, {%4,%5,%6,%7}, {%8,%9}, {%0,%1,%2,%3};" \
        : "+f"((c)[0]), "+f"((c)[1]), "+f"((c)[2]), "+f"((c)[3]) \
        : "r"(a0), "r"(a1), "r"(a2), "r"(a3), "r"(b0), "r"(b1))

// ---------------- prep: split x (transposed) and h0 ------------------------
__global__ void prep_kernel(const float* __restrict__ x, const float* __restrict__ h0)
{
    int stride = gridDim.x * blockDim.x;
    int tid0 = blockIdx.x * blockDim.x + threadIdx.x;
    // [t][b][d] <- x[b][t][d]
    for (int i = tid0; i < T_ * B_ * D_; i += stride) {
        int d = i & (D_ - 1);
        int b = (i >> 7) & (B_ - 1);
        int t = i >> 13;
        float v = x[(b * T_ + t) * D_ + d];
        __nv_bfloat16 hb = __float2bfloat16(v);
        __nv_bfloat16 lb = __float2bfloat16(v - __bfloat162float(hb));
        g_xhi[i] = __bfloat16_as_ushort(hb);
        g_xlo[i] = __bfloat16_as_ushort(lb);
    }
    for (int i = tid0; i < B_ * H_; i += stride) {
        float v = h0[i];
        __nv_bfloat16 hb = __float2bfloat16(v);
        __nv_bfloat16 lb = __float2bfloat16(v - __bfloat162float(hb));
        g_hhi[0][i] = __bfloat16_as_ushort(hb);
        g_hlo[0][i] = __bfloat16_as_ushort(lb);
    }
}

// ---------------- SMEM layout ---------------------------------------------
// zpart: [4][64][20] f32 = 20480 B
// A:     128 rows (64 hi + 64 lo) x 640 bf16, row stride 1296 B  = 165888 B
//        per row: bytes [0,1024) = h part, [1024,1280) = x part
// Bhi:   16 rows x 640 bf16, stride 1296 = 20736 B
// Blo:   16 rows x 640 bf16, stride 1296 = 20736 B
#define ASTRIDE   1296
#define SM_ZP     0
#define ZP_STRIDE 20
#define SM_A      20480
#define SM_B      (SM_A + 128 * ASTRIDE)       // 186368
#define SM_BLO_OF (16 * ASTRIDE)               // 20736
#define SMEM_TOTAL (SM_B + 2 * 16 * ASTRIDE)   // 227840

__device__ __forceinline__ float sigmoid_f(float x) {
    return 1.0f / (1.0f + __expf(-x));
}

__global__ void __launch_bounds__(NTHR, 1)
lstm_kernel(const float* __restrict__ U,    // [H][4H]
            const float* __restrict__ W,    // [D][4H]
            const float* __restrict__ bias, // [4H]
            const float* __restrict__ c0)   // [B][H]
{
    extern __shared__ char smem[];
    const uint32_t sb = smem_u32(smem);
    float* zp = (float*)(smem + SM_ZP);      // [4][64][20]

    const int tid  = threadIdx.x;
    const int wid  = tid >> 5;
    const int lane = tid & 31;
    const int cta  = blockIdx.x;

    // ---- one-time: build Bhi/Blo (16 gate-cols x 640 k), dense ----
    for (int np = 0; np < 16; ++np) {
        int col = (np & 3) * H_ + cta * 4 + (np >> 2);
        for (int k = tid; k < KTOT; k += NTHR) {
            float v = (k < H_) ? U[k * (4 * H_) + col] : W[(k - H_) * (4 * H_) + col];
            __nv_bfloat16 hb = __float2bfloat16(v);
            __nv_bfloat16 lb = __float2bfloat16(v - __bfloat162float(hb));
            *(uint16_t*)(smem + SM_B + np * ASTRIDE + k * 2) = __bfloat16_as_ushort(hb);
            *(uint16_t*)(smem + SM_B + SM_BLO_OF + np * ASTRIDE + k * 2) = __bfloat16_as_ushort(lb);
        }
    }

    // ---- per-lane persistent state (warps 0,1: lane = batch b) ----
    float c_st[4];
    float bias_r[16];
    if (wid < 2) {
        int b = wid * 32 + lane;
        #pragma unroll
        for (int jl = 0; jl < 4; ++jl)
            c_st[jl] = c0[b * H_ + cta * 4 + jl];
        #pragma unroll
        for (int n = 0; n < 16; ++n)
            bias_r[n] = bias[(n & 3) * H_ + cta * 4 + (n >> 2)];
    }

    // ---- stage x for t=0 ----
    for (int i = tid; i < 2048; i += NTHR) {
        int row = i >> 4, c = i & 15;
        uint32_t dst = sb + SM_A + row * ASTRIDE + 1024 + c * 16;
        const uint16_t* src = ((row < 64) ? g_xhi : g_xlo) + (size_t)(row & 63) * D_ + c * 8;
        cp16(dst, src);
    }
    CP_COMMIT();

    // ---- ldmatrix lane base addresses (k-byte offset added per use) ----
    const uint32_t a_lane = sb + SM_A
        + (uint32_t)((lane & 7) + ((lane >> 3) & 1) * 8) * ASTRIDE
        + (uint32_t)((lane >> 4) * 16);
    const uint32_t bhi_lane = sb + SM_B
        + (uint32_t)((lane & 7) + (lane >> 4) * 8) * ASTRIDE
        + (uint32_t)(((lane >> 3) & 1) * 16);
    const uint32_t blo_lane = bhi_lane + SM_BLO_OF;

    const uint32_t kb0 = (uint32_t)(wid * 160);   // warp k-start byte offset (80 k * 2B)

    for (int t = 0; t < T_; ++t) {
        // ---- stage h (128 rows x 64 chunks of 16B) via cp.async.cg ----
        {
            const uint16_t* hh = g_hhi[t & 1];
            const uint16_t* hl = g_hlo[t & 1];
            #pragma unroll 4
            for (int i = tid; i < 8192; i += NTHR) {
                int row = i >> 6, c = i & 63;
                uint32_t dst = sb + SM_A + row * ASTRIDE + c * 16;
                const uint16_t* src = ((row < 64) ? hh : hl) + (row & 63) * H_ + c * 8;
                cp16(dst, src);
            }
        }
        CP_COMMIT();
        CP_WAIT0();
        __syncthreads();

        // ---- MMA: warp covers all 64 b (4 m-tiles hi + 4 lo), N=16, K=80 ----
        float C[4][2][4];
        #pragma unroll
        for (int m = 0; m < 4; ++m)
            #pragma unroll
            for (int nt = 0; nt < 2; ++nt)
                #pragma unroll
                for (int i = 0; i < 4; ++i) C[m][nt][i] = 0.f;

        #pragma unroll
        for (int s = 0; s < 5; ++s) {
            const uint32_t koff = kb0 + (uint32_t)(s * 32);
            uint32_t bh0, bh1, bh2, bh3, bl0, bl1, bl2, bl3;
            LDSM_X4(bh0, bh1, bh2, bh3, bhi_lane + koff);
            LDSM_X4(bl0, bl1, bl2, bl3, blo_lane + koff);
            #pragma unroll
            for (int m = 0; m < 4; ++m) {
                uint32_t ah0, ah1, ah2, ah3, al0, al1, al2, al3;
                LDSM_X4(ah0, ah1, ah2, ah3, a_lane + (uint32_t)(m * 16 * ASTRIDE) + koff);
                LDSM_X4(al0, al1, al2, al3, a_lane + (uint32_t)((64 + m * 16) * ASTRIDE) + koff);
                MMA_BF16(C[m][0], ah0, ah1, ah2, ah3, bh0, bh1);   // hi * U_hi
                MMA_BF16(C[m][1], ah0, ah1, ah2, ah3, bh2, bh3);
                MMA_BF16(C[m][0], al0, al1, al2, al3, bh0, bh1);   // lo * U_hi
                MMA_BF16(C[m][1], al0, al1, al2, al3, bh2, bh3);
                MMA_BF16(C[m][0], ah0, ah1, ah2, ah3, bl0, bl1);   // hi * U_lo
                MMA_BF16(C[m][1], ah0, ah1, ah2, ah3, bl2, bl3);
            }
        }
        __syncthreads();   // all LDSM reads of A complete

        // ---- phase1: warps 0-3 write partials; all warps prefetch x(t+1) ----
        if (wid < 4) {
            float* zb = zp + wid * (64 * ZP_STRIDE);
            #pragma unroll
            for (int m = 0; m < 4; ++m) {
                int b0 = 16 * m + (lane >> 2);
                #pragma unroll
                for (int nt = 0; nt < 2; ++nt) {
                    int n0 = 8 * nt + 2 * (lane & 3);
                    *(float2*)(zb + b0 * ZP_STRIDE + n0)       = make_float2(C[m][nt][0], C[m][nt][1]);
                    *(float2*)(zb + (b0 + 8) * ZP_STRIDE + n0) = make_float2(C[m][nt][2], C[m][nt][3]);
                }
            }
        }
        if (t + 1 < T_) {
            const size_t xoff = (size_t)(t + 1) * B_ * D_;
            #pragma unroll 2
            for (int i = tid; i < 2048; i += NTHR) {
                int row = i >> 4, c = i & 15;
                uint32_t dst = sb + SM_A + row * ASTRIDE + 1024 + c * 16;
                const uint16_t* src = ((row < 64) ? g_xhi : g_xlo) + xoff + (size_t)(row & 63) * D_ + c * 8;
                cp16(dst, src);
            }
        }
        CP_COMMIT();
        __syncthreads();

        // ---- phase2: warps 4-7 accumulate into buffers 0-3 ----
        if (wid >= 4) {
            float* zb = zp + (wid - 4) * (64 * ZP_STRIDE);
            #pragma unroll
            for (int m = 0; m < 4; ++m) {
                int b0 = 16 * m + (lane >> 2);
                #pragma unroll
                for (int nt = 0; nt < 2; ++nt) {
                    int n0 = 8 * nt + 2 * (lane & 3);
                    float2 v0 = *(float2*)(zb + b0 * ZP_STRIDE + n0);
                    float2 v1 = *(float2*)(zb + (b0 + 8) * ZP_STRIDE + n0);
                    v0.x += C[m][nt][0]; v0.y += C[m][nt][1];
                    v1.x += C[m][nt][2]; v1.y += C[m][nt][3];
                    *(float2*)(zb + b0 * ZP_STRIDE + n0)       = v0;
                    *(float2*)(zb + (b0 + 8) * ZP_STRIDE + n0) = v1;
                }
            }
        }
        __syncthreads();

        // ---- gates (warps 0,1; lane = batch b) ----
        if (wid < 2) {
            int b = wid * 32 + lane;
            float z[16];
            #pragma unroll
            for (int n = 0; n < 16; ++n) z[n] = bias_r[n];
            #pragma unroll
            for (int wq = 0; wq < 4; ++wq) {
                const float* zb = zp + wq * (64 * ZP_STRIDE) + b * ZP_STRIDE;
                #pragma unroll
                for (int n4 = 0; n4 < 4; ++n4) {
                    float4 v = *(const float4*)(zb + n4 * 4);
                    z[n4 * 4 + 0] += v.x;
                    z[n4 * 4 + 1] += v.y;
                    z[n4 * 4 + 2] += v.z;
                    z[n4 * 4 + 3] += v.w;
                }
            }
            uint32_t hi01 = 0, hi23 = 0, lo01 = 0, lo23 = 0;
            #pragma unroll
            for (int jl = 0; jl < 4; ++jl) {
                float ig = sigmoid_f(z[jl * 4 + 0]);
                float fg = sigmoid_f(z[jl * 4 + 1]);
                float gg = tanhf(z[jl * 4 + 2]);
                float og = sigmoid_f(z[jl * 4 + 3]);
                float cn = fg * c_st[jl] + ig * gg;
                c_st[jl] = cn;
                float hn = og * tanhf(cn);
                g_hs[((size_t)t * H_ + cta * 4 + jl) * B_ + b] = hn;
                __nv_bfloat16 hb = __float2bfloat16(hn);
                __nv_bfloat16 lb = __float2bfloat16(hn - __bfloat162float(hb));
                uint32_t hu = __bfloat16_as_ushort(hb);
                uint32_t lu = __bfloat16_as_ushort(lb);
                if (jl == 0)      { hi01 |= hu;       lo01 |= lu; }
                else if (jl == 1) { hi01 |= hu << 16; lo01 |= lu << 16; }
                else if (jl == 2) { hi23 |= hu;       lo23 |= lu; }
                else              { hi23 |= hu << 16; lo23 |= lu << 16; }
            }
            int nb = (t & 1) ^ 1;
            *(uint2*)(g_hhi[nb] + b * H_ + cta * 4) = make_uint2(hi01, hi23);
            *(uint2*)(g_hlo[nb] + b * H_ + cta * 4) = make_uint2(lo01, lo23);
        }

        // ---- grid barrier ----
        __syncthreads();
        if (tid == 0) {
            __threadfence();
            unsigned gen = *(volatile unsigned*)&g_bar_gen;
            unsigned arr = atomicAdd(&g_bar_cnt, 1u);
            if (arr == NCTA - 1) {
                g_bar_cnt = 0;
                __threadfence();
                atomicAdd(&g_bar_gen, 1u);
            } else {
                while (*(volatile unsigned*)&g_bar_gen == gen) { }
            }
            __threadfence();
        }
        __syncthreads();
    }
}

// ---------------- output projection: out[b,t,o] = hs[t,:,b] . Wo[:,o] + bo --
__global__ void __launch_bounds__(256) proj_kernel(
    const float* __restrict__ Wo,   // [H][O]
    const float* __restrict__ bo,   // [O]
    float* __restrict__ out)        // [B][T][O]
{
    __shared__ float4 a_s[64 * 16];
    __shared__ float4 w_s[64 * 16];
    const int t   = blockIdx.x;
    const int ot  = blockIdx.y;
    const int tid = threadIdx.x;
    const int tb  = tid & 15;
    const int to  = tid >> 4;

    float acc[4][4];
    #pragma unroll
    for (int r = 0; r < 4; ++r)
        #pragma unroll
        for (int cc = 0; cc < 4; ++cc) acc[r][cc] = 0.0f;

    for (int jc = 0; jc < H_ / 64; ++jc) {
        const float4* asrc = (const float4*)(g_hs + ((size_t)t * H_ + jc * 64) * B_);
        #pragma unroll
        for (int i = tid; i < 64 * 16; i += 256) a_s[i] = asrc[i];
        #pragma unroll
        for (int i = tid; i < 64 * 16; i += 256) {
            int jj = i >> 4, o4 = i & 15;
            w_s[i] = *(const float4*)(Wo + (jc * 64 + jj) * O_ + ot * 64 + o4 * 4);
        }
        __syncthreads();
        #pragma unroll 8
        for (int jj = 0; jj < 64; ++jj) {
            float4 av = a_s[jj * 16 + tb];
            float4 wv = w_s[jj * 16 + to];
            acc[0][0] = fmaf(av.x, wv.x, acc[0][0]);
            acc[0][1] = fmaf(av.x, wv.y, acc[0][1]);
            acc[0][2] = fmaf(av.x, wv.z, acc[0][2]);
            acc[0][3] = fmaf(av.x, wv.w, acc[0][3]);
            acc[1][0] = fmaf(av.y, wv.x, acc[1][0]);
            acc[1][1] = fmaf(av.y, wv.y, acc[1][1]);
            acc[1][2] = fmaf(av.y, wv.z, acc[1][2]);
            acc[1][3] = fmaf(av.y, wv.w, acc[1][3]);
            acc[2][0] = fmaf(av.z, wv.x, acc[2][0]);
            acc[2][1] = fmaf(av.z, wv.y, acc[2][1]);
            acc[2][2] = fmaf(av.z, wv.z, acc[2][2]);
            acc[2][3] = fmaf(av.z, wv.w, acc[2][3]);
            acc[3][0] = fmaf(av.w, wv.x, acc[3][0]);
            acc[3][1] = fmaf(av.w, wv.y, acc[3][1]);
            acc[3][2] = fmaf(av.w, wv.z, acc[3][2]);
            acc[3][3] = fmaf(av.w, wv.w, acc[3][3]);
        }
        __syncthreads();
    }

    const int obase = ot * 64 + to * 4;
    float4 bv = *(const float4*)(bo + obase);
    #pragma unroll
    for (int r = 0; r < 4; ++r) {
        int bb = tb * 4 + r;
        float4 v = make_float4(acc[r][0] + bv.x, acc[r][1] + bv.y,
                               acc[r][2] + bv.z, acc[r][3] + bv.w);
        *(float4*)(out + ((size_t)bb * T_ + t) * O_ + obase) = v;
    }
}

// ---------------- launch --------------------------------------------------
extern "C" void kernel_launch(void* const* d_in, const int* in_sizes, int n_in,
                              void* d_out, int out_size)
{
    const float* x   = (const float*)d_in[0];
    const float* h0  = (const float*)d_in[1];
    const float* c0  = (const float*)d_in[2];
    const float* W   = (const float*)d_in[3];
    const float* U   = (const float*)d_in[4];
    const float* bia = (const float*)d_in[5];
    const float* Wo  = (const float*)d_in[6];
    const float* bo  = (const float*)d_in[7];
    float* out = (float*)d_out;
    (void)in_sizes; (void)n_in; (void)out_size;

    cudaFuncSetAttribute(lstm_kernel,
                         cudaFuncAttributeMaxDynamicSharedMemorySize, SMEM_TOTAL);

    prep_kernel<<<1024, 256>>>(x, h0);
    lstm_kernel<<<NCTA, NTHR, SMEM_TOTAL>>>(U, W, bia, c0);
    dim3 pg(T_, O_ / 64);
    proj_kernel<<<pg, 256>>>(Wo, bo, out);
}

// round 5
// speedup vs baseline: 2.6522x; 1.4421x over previous
#include <cuda_runtime.h>
#include <cuda_bf16.h>
#include <cstdint>

// Problem constants
#define B_  64
#define T_  512
#define D_  128
#define H_  512
#define O_  256

#define NCTA 128          // 4 batch-groups x 32 j-groups
#define NTHR 256          // 8 warps
#define KTOT 640          // K = H + D

// ---------------- device scratch ------------------------------------------
__device__ uint16_t g_hhi[2][B_ * H_];     // bf16 hi of h, [buf][b][j]
__device__ uint16_t g_hlo[2][B_ * H_];     // bf16 lo of h
__device__ uint16_t g_xhi[T_ * B_ * D_];   // bf16 hi of x, [t][b][d]
__device__ uint16_t g_xlo[T_ * B_ * D_];
__device__ float    g_hs[T_ * H_ * B_];    // hidden states [t][j][b] for proj
__device__ unsigned g_bar_cnt;
__device__ unsigned g_bar_gen;

// ---------------- PTX helpers ---------------------------------------------
__device__ __forceinline__ uint32_t smem_u32(const void* p) {
    uint32_t a;
    asm("{ .reg .u64 t; cvta.to.shared.u64 t, %1; cvt.u32.u64 %0, t; }" : "=r"(a) : "l"(p));
    return a;
}
__device__ __forceinline__ void cp16(uint32_t s, const void* g) {
    asm volatile("cp.async.cg.shared.global [%0], [%1], 16;" :: "r"(s), "l"(g));
}
#define CP_COMMIT() asm volatile("cp.async.commit_group;" ::: "memory")
#define CP_WAIT0()  asm volatile("cp.async.wait_group 0;" ::: "memory")

#define LDSM_X4(r0, r1, r2, r3, addr) \
    asm volatile("ldmatrix.sync.aligned.m8n8.x4.shared.b16 {%0,%1,%2,%3}, [%4];" \
        : "=r"(r0), "=r"(r1), "=r"(r2), "=r"(r3) : "r"(addr))

#define MMA_BF16(c, a0, a1, a2, a3, b0, b1) \
    asm volatile("mma.sync.aligned.m16n8k16.row.col.f32.bf16.bf16.f32 " \
        "{%0,%1,%2,%3}, {%4,%5,%6,%7}, {%8,%9}, {%0,%1,%2,%3};" \
        : "+f"((c)[0]), "+f"((c)[1]), "+f"((c)[2]), "+f"((c)[3]) \
        : "r"(a0), "r"(a1), "r"(a2), "r"(a3), "r"(b0), "r"(b1))

// fast gate functions (MUFU-based regardless of compile flags)
__device__ __forceinline__ float sig_f(float x) {
    return __fdividef(1.0f, 1.0f + __expf(-x));
}
__device__ __forceinline__ float tanh_f(float x) {
    return __fdividef(2.0f, 1.0f + __expf(-2.0f * x)) - 1.0f;
}

// ---------------- prep: split x (transposed) and h0 ------------------------
__global__ void prep_kernel(const float* __restrict__ x, const float* __restrict__ h0)
{
    int stride = gridDim.x * blockDim.x;
    int tid0 = blockIdx.x * blockDim.x + threadIdx.x;
    for (int i = tid0; i < T_ * B_ * D_; i += stride) {
        int d = i & (D_ - 1);
        int b = (i >> 7) & (B_ - 1);
        int t = i >> 13;
        float v = x[(b * T_ + t) * D_ + d];
        __nv_bfloat16 hb = __float2bfloat16(v);
        __nv_bfloat16 lb = __float2bfloat16(v - __bfloat162float(hb));
        g_xhi[i] = __bfloat16_as_ushort(hb);
        g_xlo[i] = __bfloat16_as_ushort(lb);
    }
    for (int i = tid0; i < B_ * H_; i += stride) {
        float v = h0[i];
        __nv_bfloat16 hb = __float2bfloat16(v);
        __nv_bfloat16 lb = __float2bfloat16(v - __bfloat162float(hb));
        g_hhi[0][i] = __bfloat16_as_ushort(hb);
        g_hlo[0][i] = __bfloat16_as_ushort(lb);
    }
}

// ---------------- SMEM layout ---------------------------------------------
// zp: 4 buffers x [16 b][68] f32 = 17408 B
// A : 32 rows (16 b-hi + 16 b-lo) x 640 bf16, stride 1296 B = 41472 B
//     per row: [0,1024) = h (k<512), [1024,1280) = x
// B : 128 rows (64 gate-col hi + 64 lo) x 640 bf16, stride 1296 B = 165888 B
#define ASTRIDE   1296
#define ZSTR      68
#define ZPBUF     (16 * ZSTR)                  // floats per buffer
#define SM_ZP     0
#define SM_A      17408
#define SM_B      (SM_A + 32 * ASTRIDE)        // 58880
#define SMEM_TOTAL (SM_B + 128 * ASTRIDE)      // 224768

__global__ void __launch_bounds__(NTHR, 1)
lstm_kernel(const float* __restrict__ U,    // [H][4H]
            const float* __restrict__ W,    // [D][4H]
            const float* __restrict__ bias, // [4H]
            const float* __restrict__ c0)   // [B][H]
{
    extern __shared__ char smem[];
    const uint32_t sb = smem_u32(smem);
    float* zp = (float*)(smem + SM_ZP);

    const int tid  = threadIdx.x;
    const int wid  = tid >> 5;
    const int lane = tid & 31;
    const int bg   = blockIdx.x & 3;     // batch-group: batches bg*16..+15
    const int jg   = blockIdx.x >> 2;    // j-group: hidden units jg*16..+15

    // ---- one-time: build B (64 hi cols + 64 lo cols) x 640 k ----
    for (int n = 0; n < 128; ++n) {
        int np  = n & 63;
        int col = (np & 3) * H_ + jg * 16 + (np >> 2);
        for (int k = tid; k < KTOT; k += NTHR) {
            float v = (k < H_) ? U[k * (4 * H_) + col] : W[(k - H_) * (4 * H_) + col];
            __nv_bfloat16 hb = __float2bfloat16(v);
            uint16_t outv;
            if (n < 64) outv = __bfloat16_as_ushort(hb);
            else {
                __nv_bfloat16 lb = __float2bfloat16(v - __bfloat162float(hb));
                outv = __bfloat16_as_ushort(lb);
            }
            *(uint16_t*)(smem + SM_B + n * ASTRIDE + k * 2) = outv;
        }
    }

    // ---- per-thread persistent state: thread = (b = tid>>4, jl = tid&15) ----
    const int tb = tid >> 4;     // local batch 0..15
    const int tj = tid & 15;     // local hidden unit 0..15
    const int gb = bg * 16 + tb; // global batch
    const int gj = jg * 16 + tj; // global hidden unit
    float c_st = c0[gb * H_ + gj];
    const float bi  = bias[gj];
    const float bf  = bias[H_ + gj];
    const float bgc = bias[2 * H_ + gj];
    const float bo_ = bias[3 * H_ + gj];

    // ---- stage x for t=0 (32 rows x 16 chunks of 16B) ----
    for (int i = tid; i < 512; i += NTHR) {
        int row = i >> 4, c = i & 15;
        uint32_t dst = sb + SM_A + row * ASTRIDE + 1024 + c * 16;
        const uint16_t* src = ((row < 16) ? g_xhi : g_xlo)
                            + ((size_t)0 * B_ + bg * 16 + (row & 15)) * D_ + c * 8;
        cp16(dst, src);
    }
    CP_COMMIT();

    // ---- ldmatrix lane base addresses ----
    const uint32_t a_lane = sb + SM_A
        + (uint32_t)((lane & 7) + ((lane >> 3) & 1) * 8) * ASTRIDE
        + (uint32_t)((lane >> 4) * 16);
    const uint32_t b_lane = sb + SM_B
        + (uint32_t)((lane & 7) + (lane >> 4) * 8) * ASTRIDE
        + (uint32_t)(((lane >> 3) & 1) * 16);
    const uint32_t kb0 = (uint32_t)(wid * 160);   // warp K-slice (80 k) byte offset

    for (int t = 0; t < T_; ++t) {
        // ---- stage h: 32 rows x 64 chunks of 16B via cp.async.cg ----
        {
            const uint16_t* hh = g_hhi[t & 1];
            const uint16_t* hl = g_hlo[t & 1];
            #pragma unroll
            for (int i = tid; i < 2048; i += NTHR) {
                int row = i >> 6, c = i & 63;
                uint32_t dst = sb + SM_A + row * ASTRIDE + c * 16;
                const uint16_t* src = ((row < 16) ? hh : hl)
                                    + (bg * 16 + (row & 15)) * H_ + c * 8;
                cp16(dst, src);
            }
        }
        CP_COMMIT();
        CP_WAIT0();
        __syncthreads();

        // ---- MMA: M=32 (b hi+lo), N=128 (gate-col hi+lo), K-slice 80 per warp ----
        float C[8][4];
        #pragma unroll
        for (int nt = 0; nt < 8; ++nt)
            #pragma unroll
            for (int i = 0; i < 4; ++i) C[nt][i] = 0.f;

        #pragma unroll
        for (int s = 0; s < 5; ++s) {
            const uint32_t koff = kb0 + (uint32_t)(s * 32);
            uint32_t ah0, ah1, ah2, ah3, al0, al1, al2, al3;
            LDSM_X4(ah0, ah1, ah2, ah3, a_lane + koff);                          // b-hi rows
            LDSM_X4(al0, al1, al2, al3, a_lane + 16u * ASTRIDE + koff);          // b-lo rows
            #pragma unroll
            for (int g = 0; g < 4; ++g) {
                uint32_t bh0, bh1, bh2, bh3, bl0, bl1, bl2, bl3;
                LDSM_X4(bh0, bh1, bh2, bh3, b_lane + (uint32_t)(g * 16 * ASTRIDE) + koff);
                LDSM_X4(bl0, bl1, bl2, bl3, b_lane + (uint32_t)((64 + g * 16) * ASTRIDE) + koff);
                // n-tile 2g : cols g*16..+7 ; n-tile 2g+1 : cols g*16+8..+15
                MMA_BF16(C[2 * g],     ah0, ah1, ah2, ah3, bh0, bh1);   // hi*Uhi
                MMA_BF16(C[2 * g],     al0, al1, al2, al3, bh0, bh1);   // lo*Uhi
                MMA_BF16(C[2 * g],     ah0, ah1, ah2, ah3, bl0, bl1);   // hi*Ulo
                MMA_BF16(C[2 * g + 1], ah0, ah1, ah2, ah3, bh2, bh3);
                MMA_BF16(C[2 * g + 1], al0, al1, al2, al3, bh2, bh3);
                MMA_BF16(C[2 * g + 1], ah0, ah1, ah2, ah3, bl2, bl3);
            }
        }
        __syncthreads();   // all LDSM reads of A/B for this step complete

        // ---- phase1: warps 0-3 write K-partials; all threads prefetch x(t+1) ----
        if (wid < 4) {
            float* zb = zp + wid * ZPBUF;
            int r0 = lane >> 2;
            int cc = 2 * (lane & 3);
            #pragma unroll
            for (int nt = 0; nt < 8; ++nt) {
                int n0 = nt * 8 + cc;
                *(float2*)(zb + r0 * ZSTR + n0)       = make_float2(C[nt][0], C[nt][1]);
                *(float2*)(zb + (r0 + 8) * ZSTR + n0) = make_float2(C[nt][2], C[nt][3]);
            }
        }
        if (t + 1 < T_) {
            const size_t xoff = (size_t)(t + 1) * B_ * D_;
            #pragma unroll
            for (int i = tid; i < 512; i += NTHR) {
                int row = i >> 4, c = i & 15;
                uint32_t dst = sb + SM_A + row * ASTRIDE + 1024 + c * 16;
                const uint16_t* src = ((row < 16) ? g_xhi : g_xlo)
                                    + xoff + (size_t)(bg * 16 + (row & 15)) * D_ + c * 8;
                cp16(dst, src);
            }
        }
        CP_COMMIT();
        __syncthreads();

        // ---- phase2: warps 4-7 accumulate into buffers 0-3 ----
        if (wid >= 4) {
            float* zb = zp + (wid - 4) * ZPBUF;
            int r0 = lane >> 2;
            int cc = 2 * (lane & 3);
            #pragma unroll
            for (int nt = 0; nt < 8; ++nt) {
                int n0 = nt * 8 + cc;
                float2 v0 = *(float2*)(zb + r0 * ZSTR + n0);
                float2 v1 = *(float2*)(zb + (r0 + 8) * ZSTR + n0);
                v0.x += C[nt][0]; v0.y += C[nt][1];
                v1.x += C[nt][2]; v1.y += C[nt][3];
                *(float2*)(zb + r0 * ZSTR + n0)       = v0;
                *(float2*)(zb + (r0 + 8) * ZSTR + n0) = v1;
            }
        }
        __syncthreads();

        // ---- gates: one thread per (b, j) ----
        {
            float zi = bi, zf = bf, zg = bgc, zo = bo_;
            #pragma unroll
            for (int q = 0; q < 4; ++q) {
                float4 v = *(const float4*)(zp + q * ZPBUF + tb * ZSTR + tj * 4);
                zi += v.x; zf += v.y; zg += v.z; zo += v.w;
            }
            float ig = sig_f(zi);
            float fg = sig_f(zf);
            float gg = tanh_f(zg);
            float og = sig_f(zo);
            float cn = fg * c_st + ig * gg;
            c_st = cn;
            float hn = og * tanh_f(cn);
            g_hs[((size_t)t * H_ + gj) * B_ + gb] = hn;
            __nv_bfloat16 hb = __float2bfloat16(hn);
            __nv_bfloat16 lb = __float2bfloat16(hn - __bfloat162float(hb));
            int nb = (t & 1) ^ 1;
            g_hhi[nb][gb * H_ + gj] = __bfloat16_as_ushort(hb);
            g_hlo[nb][gb * H_ + gj] = __bfloat16_as_ushort(lb);
        }

        // ---- grid barrier ----
        __syncthreads();
        if (tid == 0) {
            __threadfence();
            unsigned gen = *(volatile unsigned*)&g_bar_gen;
            unsigned arr = atomicAdd(&g_bar_cnt, 1u);
            if (arr == NCTA - 1) {
                g_bar_cnt = 0;
                __threadfence();
                atomicAdd(&g_bar_gen, 1u);
            } else {
                while (*(volatile unsigned*)&g_bar_gen == gen) { }
            }
            __threadfence();
        }
        __syncthreads();
    }
}

// ---------------- output projection: out[b,t,o] = hs[t,:,b] . Wo[:,o] + bo --
__global__ void __launch_bounds__(256) proj_kernel(
    const float* __restrict__ Wo,   // [H][O]
    const float* __restrict__ bo,   // [O]
    float* __restrict__ out)        // [B][T][O]
{
    __shared__ float4 a_s[64 * 16];
    __shared__ float4 w_s[64 * 16];
    const int t   = blockIdx.x;
    const int ot  = blockIdx.y;
    const int tid = threadIdx.x;
    const int tb  = tid & 15;
    const int to  = tid >> 4;

    float acc[4][4];
    #pragma unroll
    for (int r = 0; r < 4; ++r)
        #pragma unroll
        for (int cc = 0; cc < 4; ++cc) acc[r][cc] = 0.0f;

    for (int jc = 0; jc < H_ / 64; ++jc) {
        const float4* asrc = (const float4*)(g_hs + ((size_t)t * H_ + jc * 64) * B_);
        #pragma unroll
        for (int i = tid; i < 64 * 16; i += 256) a_s[i] = asrc[i];
        #pragma unroll
        for (int i = tid; i < 64 * 16; i += 256) {
            int jj = i >> 4, o4 = i & 15;
            w_s[i] = *(const float4*)(Wo + (jc * 64 + jj) * O_ + ot * 64 + o4 * 4);
        }
        __syncthreads();
        #pragma unroll 8
        for (int jj = 0; jj < 64; ++jj) {
            float4 av = a_s[jj * 16 + tb];
            float4 wv = w_s[jj * 16 + to];
            acc[0][0] = fmaf(av.x, wv.x, acc[0][0]);
            acc[0][1] = fmaf(av.x, wv.y, acc[0][1]);
            acc[0][2] = fmaf(av.x, wv.z, acc[0][2]);
            acc[0][3] = fmaf(av.x, wv.w, acc[0][3]);
            acc[1][0] = fmaf(av.y, wv.x, acc[1][0]);
            acc[1][1] = fmaf(av.y, wv.y, acc[1][1]);
            acc[1][2] = fmaf(av.y, wv.z, acc[1][2]);
            acc[1][3] = fmaf(av.y, wv.w, acc[1][3]);
            acc[2][0] = fmaf(av.z, wv.x, acc[2][0]);
            acc[2][1] = fmaf(av.z, wv.y, acc[2][1]);
            acc[2][2] = fmaf(av.z, wv.z, acc[2][2]);
            acc[2][3] = fmaf(av.z, wv.w, acc[2][3]);
            acc[3][0] = fmaf(av.w, wv.x, acc[3][0]);
            acc[3][1] = fmaf(av.w, wv.y, acc[3][1]);
            acc[3][2] = fmaf(av.w, wv.z, acc[3][2]);
            acc[3][3] = fmaf(av.w, wv.w, acc[3][3]);
        }
        __syncthreads();
    }

    const int obase = ot * 64 + to * 4;
    float4 bv = *(const float4*)(bo + obase);
    #pragma unroll
    for (int r = 0; r < 4; ++r) {
        int bb = tb * 4 + r;
        float4 v = make_float4(acc[r][0] + bv.x, acc[r][1] + bv.y,
                               acc[r][2] + bv.z, acc[r][3] + bv.w);
        *(float4*)(out + ((size_t)bb * T_ + t) * O_ + obase) = v;
    }
}

// ---------------- launch --------------------------------------------------
extern "C" void kernel_launch(void* const* d_in, const int* in_sizes, int n_in,
                              void* d_out, int out_size)
{
    const float* x   = (const float*)d_in[0];
    const float* h0  = (const float*)d_in[1];
    const float* c0  = (const float*)d_in[2];
    const float* W   = (const float*)d_in[3];
    const float* U   = (const float*)d_in[4];
    const float* bia = (const float*)d_in[5];
    const float* Wo  = (const float*)d_in[6];
    const float* bo  = (const float*)d_in[7];
    float* out = (float*)d_out;
    (void)in_sizes; (void)n_in; (void)out_size;

    cudaFuncSetAttribute(lstm_kernel,
                         cudaFuncAttributeMaxDynamicSharedMemorySize, SMEM_TOTAL);

    prep_kernel<<<1024, 256>>>(x, h0);
    lstm_kernel<<<NCTA, NTHR, SMEM_TOTAL>>>(U, W, bia, c0);
    dim3 pg(T_, O_ / 64);
    proj_kernel<<<pg, 256>>>(Wo, bo, out);
}

// round 6
// speedup vs baseline: 3.4627x; 1.3056x over previous
#include <cuda_runtime.h>
#include <cuda_bf16.h>
#include <cstdint>

// Problem constants
#define B_  64
#define T_  512
#define D_  128
#define H_  512
#define O_  256

#define NCTA 128          // 4 batch-groups x 32 j-groups
#define NTHR 256          // 8 warps
#define KTOT 640          // K = H + D

// ---------------- device scratch ------------------------------------------
// h history as bf16 splits, [t][b][j]; slice 0 = h0, slice t+1 = output of step t
__device__ uint16_t g_hshi[(T_ + 1) * B_ * H_];
__device__ uint16_t g_hslo[(T_ + 1) * B_ * H_];
__device__ uint16_t g_xhi[T_ * B_ * D_];   // bf16 hi of x, [t][b][d]
__device__ uint16_t g_xlo[T_ * B_ * D_];
__device__ unsigned g_bar4[4];             // per-batch-group monotonic barrier counters

// ---------------- PTX helpers ---------------------------------------------
__device__ __forceinline__ uint32_t smem_u32(const void* p) {
    uint32_t a;
    asm("{ .reg .u64 t; cvta.to.shared.u64 t, %1; cvt.u32.u64 %0, t; }" : "=r"(a) : "l"(p));
    return a;
}
__device__ __forceinline__ void cp16(uint32_t s, const void* g) {
    asm volatile("cp.async.cg.shared.global [%0], [%1], 16;" :: "r"(s), "l"(g));
}
#define CP_COMMIT() asm volatile("cp.async.commit_group;" ::: "memory")
#define CP_WAIT0()  asm volatile("cp.async.wait_group 0;" ::: "memory")

#define LDSM_X4(r0, r1, r2, r3, addr) \
    asm volatile("ldmatrix.sync.aligned.m8n8.x4.shared.b16 {%0,%1,%2,%3}, [%4];" \
        : "=r"(r0), "=r"(r1), "=r"(r2), "=r"(r3) : "r"(addr))

#define MMA_BF16(c, a0, a1, a2, a3, b0, b1) \
    asm volatile("mma.sync.aligned.m16n8k16.row.col.f32.bf16.bf16.f32 " \
        "{%0,%1,%2,%3}, {%4,%5,%6,%7}, {%8,%9}, {%0,%1,%2,%3};" \
        : "+f"((c)[0]), "+f"((c)[1]), "+f"((c)[2]), "+f"((c)[3]) \
        : "r"(a0), "r"(a1), "r"(a2), "r"(a3), "r"(b0), "r"(b1))

__device__ __forceinline__ float sig_f(float x) {
    return __fdividef(1.0f, 1.0f + __expf(-x));
}
__device__ __forceinline__ float tanh_f(float x) {
    return __fdividef(2.0f, 1.0f + __expf(-2.0f * x)) - 1.0f;
}

// ---------------- prep: split x (transposed), h0 -> slice 0, reset barriers -
__global__ void prep_kernel(const float* __restrict__ x, const float* __restrict__ h0)
{
    int stride = gridDim.x * blockDim.x;
    int tid0 = blockIdx.x * blockDim.x + threadIdx.x;
    if (tid0 < 4) g_bar4[tid0] = 0;
    for (int i = tid0; i < T_ * B_ * D_; i += stride) {
        int d = i & (D_ - 1);
        int b = (i >> 7) & (B_ - 1);
        int t = i >> 13;
        float v = x[(b * T_ + t) * D_ + d];
        __nv_bfloat16 hb = __float2bfloat16(v);
        __nv_bfloat16 lb = __float2bfloat16(v - __bfloat162float(hb));
        g_xhi[i] = __bfloat16_as_ushort(hb);
        g_xlo[i] = __bfloat16_as_ushort(lb);
    }
    for (int i = tid0; i < B_ * H_; i += stride) {
        float v = h0[i];
        __nv_bfloat16 hb = __float2bfloat16(v);
        __nv_bfloat16 lb = __float2bfloat16(v - __bfloat162float(hb));
        g_hshi[i] = __bfloat16_as_ushort(hb);
        g_hslo[i] = __bfloat16_as_ushort(lb);
    }
}

// ---------------- lstm SMEM layout ----------------------------------------
// zp buffers 0-3: [16 b][68] f32 each = 17408 B
// A : 32 rows (16 b-hi + 16 b-lo) x 640 bf16, stride 1296 B = 41472 B
//     per row: [0,1024) = h, [1024,1280) = x
// B : 128 rows x 640 bf16, stride 1296 = 165888 B (only used at init; region
//     is reused as zp buffers 4-7 once B fragments live in registers)
#define ASTRIDE   1296
#define ZSTR      68
#define ZPBUF     (16 * ZSTR)
#define SM_ZP     0
#define SM_A      17408
#define SM_B      (SM_A + 32 * ASTRIDE)        // 58880
#define SMEM_TOTAL (SM_B + 128 * ASTRIDE)      // 224768

__global__ void __launch_bounds__(NTHR, 1)
lstm_kernel(const float* __restrict__ U,    // [H][4H]
            const float* __restrict__ W,    // [D][4H]
            const float* __restrict__ bias, // [4H]
            const float* __restrict__ c0)   // [B][H]
{
    extern __shared__ char smem[];
    const uint32_t sb = smem_u32(smem);

    const int tid  = threadIdx.x;
    const int wid  = tid >> 5;
    const int lane = tid & 31;
    const int bg   = blockIdx.x & 3;     // batch-group
    const int jg   = blockIdx.x >> 2;    // j-group

    // ---- one-time: build B in smem (64 hi cols + 64 lo cols) x 640 k ----
    for (int n = 0; n < 128; ++n) {
        int np  = n & 63;
        int col = (np & 3) * H_ + jg * 16 + (np >> 2);
        for (int k = tid; k < KTOT; k += NTHR) {
            float v = (k < H_) ? U[k * (4 * H_) + col] : W[(k - H_) * (4 * H_) + col];
            __nv_bfloat16 hb = __float2bfloat16(v);
            uint16_t outv;
            if (n < 64) outv = __bfloat16_as_ushort(hb);
            else {
                __nv_bfloat16 lb = __float2bfloat16(v - __bfloat162float(hb));
                outv = __bfloat16_as_ushort(lb);
            }
            *(uint16_t*)(smem + SM_B + n * ASTRIDE + k * 2) = outv;
        }
    }

    // ---- per-thread persistent state: thread = (b = tid>>4, j = tid&15) ----
    const int tb = tid >> 4;
    const int tj = tid & 15;
    const int gb = bg * 16 + tb;
    const int gj = jg * 16 + tj;
    float c_st = c0[gb * H_ + gj];
    const float bi  = bias[gj];
    const float bf  = bias[H_ + gj];
    const float bgc = bias[2 * H_ + gj];
    const float bo_ = bias[3 * H_ + gj];

    // ---- stage x for t=0 ----
    for (int i = tid; i < 512; i += NTHR) {
        int row = i >> 4, c = i & 15;
        uint32_t dst = sb + SM_A + row * ASTRIDE + 1024 + c * 16;
        const uint16_t* src = ((row < 16) ? g_xhi : g_xlo)
                            + (size_t)(bg * 16 + (row & 15)) * D_ + c * 8;
        cp16(dst, src);
    }
    CP_COMMIT();

    // ---- ldmatrix lane base addresses ----
    const uint32_t a_lane = sb + SM_A
        + (uint32_t)((lane & 7) + ((lane >> 3) & 1) * 8) * ASTRIDE
        + (uint32_t)((lane >> 4) * 16);
    const uint32_t b_lane = sb + SM_B
        + (uint32_t)((lane & 7) + (lane >> 4) * 8) * ASTRIDE
        + (uint32_t)(((lane >> 3) & 1) * 16);
    const uint32_t kb0 = (uint32_t)(wid * 160);   // warp K-slice (80 k) byte offset

    // ---- hoist loop-invariant B fragments into registers (40 LDSM_X4) ----
    __syncthreads();   // B build complete
    uint32_t Bh[5][4][4], Bl[5][4][4];
    #pragma unroll
    for (int s = 0; s < 5; ++s) {
        const uint32_t koff = kb0 + (uint32_t)(s * 32);
        #pragma unroll
        for (int g = 0; g < 4; ++g) {
            LDSM_X4(Bh[s][g][0], Bh[s][g][1], Bh[s][g][2], Bh[s][g][3],
                    b_lane + (uint32_t)(g * 16 * ASTRIDE) + koff);
            LDSM_X4(Bl[s][g][0], Bl[s][g][1], Bl[s][g][2], Bl[s][g][3],
                    b_lane + (uint32_t)((64 + g * 16) * ASTRIDE) + koff);
        }
    }

    for (int t = 0; t < T_; ++t) {
        // ---- stage h slice t: 32 rows x 64 chunks of 16B ----
        {
            const size_t hoff = (size_t)t * B_ * H_;
            #pragma unroll
            for (int i = tid; i < 2048; i += NTHR) {
                int row = i >> 6, c = i & 63;
                uint32_t dst = sb + SM_A + row * ASTRIDE + c * 16;
                const uint16_t* src = ((row < 16) ? g_hshi : g_hslo)
                                    + hoff + (size_t)(bg * 16 + (row & 15)) * H_ + c * 8;
                cp16(dst, src);
            }
        }
        CP_COMMIT();
        CP_WAIT0();
        __syncthreads();                                  // [1]

        // ---- MMA: M=32 (b hi+lo), N=64 gate-cols (+lo-weight term), K=80/warp ----
        float C[8][4];
        #pragma unroll
        for (int nt = 0; nt < 8; ++nt)
            #pragma unroll
            for (int i = 0; i < 4; ++i) C[nt][i] = 0.f;

        #pragma unroll
        for (int s = 0; s < 5; ++s) {
            const uint32_t koff = kb0 + (uint32_t)(s * 32);
            uint32_t ah0, ah1, ah2, ah3, al0, al1, al2, al3;
            LDSM_X4(ah0, ah1, ah2, ah3, a_lane + koff);
            LDSM_X4(al0, al1, al2, al3, a_lane + 16u * ASTRIDE + koff);
            #pragma unroll
            for (int g = 0; g < 4; ++g) {
                MMA_BF16(C[2 * g],     ah0, ah1, ah2, ah3, Bh[s][g][0], Bh[s][g][1]);
                MMA_BF16(C[2 * g],     al0, al1, al2, al3, Bh[s][g][0], Bh[s][g][1]);
                MMA_BF16(C[2 * g],     ah0, ah1, ah2, ah3, Bl[s][g][0], Bl[s][g][1]);
                MMA_BF16(C[2 * g + 1], ah0, ah1, ah2, ah3, Bh[s][g][2], Bh[s][g][3]);
                MMA_BF16(C[2 * g + 1], al0, al1, al2, al3, Bh[s][g][2], Bh[s][g][3]);
                MMA_BF16(C[2 * g + 1], ah0, ah1, ah2, ah3, Bl[s][g][2], Bl[s][g][3]);
            }
        }
        __syncthreads();                                  // [2] A reads done

        // ---- all 8 warps write K-partials; prefetch x(t+1) ----
        {
            float* zb = (wid < 4)
                ? (float*)(smem + SM_ZP) + wid * ZPBUF
                : (float*)(smem + SM_B) + (wid - 4) * ZPBUF;
            int r0 = lane >> 2;
            int cc = 2 * (lane & 3);
            #pragma unroll
            for (int nt = 0; nt < 8; ++nt) {
                int n0 = nt * 8 + cc;
                *(float2*)(zb + r0 * ZSTR + n0)       = make_float2(C[nt][0], C[nt][1]);
                *(float2*)(zb + (r0 + 8) * ZSTR + n0) = make_float2(C[nt][2], C[nt][3]);
            }
        }
        if (t + 1 < T_) {
            const size_t xoff = (size_t)(t + 1) * B_ * D_;
            #pragma unroll
            for (int i = tid; i < 512; i += NTHR) {
                int row = i >> 4, c = i & 15;
                uint32_t dst = sb + SM_A + row * ASTRIDE + 1024 + c * 16;
                const uint16_t* src = ((row < 16) ? g_xhi : g_xlo)
                                    + xoff + (size_t)(bg * 16 + (row & 15)) * D_ + c * 8;
                cp16(dst, src);
            }
        }
        CP_COMMIT();
        __syncthreads();                                  // [3]

        // ---- gates: one thread per (b, j); sum 8 partial buffers ----
        {
            float zi = bi, zf = bf, zg = bgc, zo = bo_;
            #pragma unroll
            for (int q = 0; q < 8; ++q) {
                const float* zb = (q < 4)
                    ? (const float*)(smem + SM_ZP) + q * ZPBUF
                    : (const float*)(smem + SM_B) + (q - 4) * ZPBUF;
                float4 v = *(const float4*)(zb + tb * ZSTR + tj * 4);
                zi += v.x; zf += v.y; zg += v.z; zo += v.w;
            }
            float ig = sig_f(zi);
            float fg = sig_f(zf);
            float gg = tanh_f(zg);
            float og = sig_f(zo);
            float cn = fg * c_st + ig * gg;
            c_st = cn;
            float hn = og * tanh_f(cn);
            __nv_bfloat16 hb = __float2bfloat16(hn);
            __nv_bfloat16 lb = __float2bfloat16(hn - __bfloat162float(hb));
            size_t idx = ((size_t)(t + 1) * B_ + gb) * H_ + gj;
            g_hshi[idx] = __bfloat16_as_ushort(hb);
            g_hslo[idx] = __bfloat16_as_ushort(lb);
        }

        // ---- per-batch-group barrier (32 CTAs, monotonic counter) ----
        __syncthreads();                                  // [4] all h writes done
        if (tid == 0) {
            __threadfence();
            atomicAdd(&g_bar4[bg], 1u);
            unsigned target = 32u * (unsigned)(t + 1);
            while (*(volatile unsigned*)&g_bar4[bg] < target) { }
            __threadfence();
        }
        __syncthreads();                                  // [5]
    }
}

// ---------------- HMMA output projection ----------------------------------
// block = (t, og): C[64 b][64 o] = hs(t+1)[b][:] . Wo[:, og*64..+63] + bo
// 3-term split-bf16; K=512 in 4 chunks of 128.
#define PSTRIDE 272
#define SMP_A   0
#define SMP_B   (128 * PSTRIDE)                 // 34816
#define SMEM_PROJ (SMP_B + 128 * PSTRIDE)       // 69632

__global__ void __launch_bounds__(256) proj_kernel(
    const float* __restrict__ Wo,   // [H][O]
    const float* __restrict__ bo,   // [O]
    float* __restrict__ out)        // [B][T][O]
{
    extern __shared__ char smem[];
    const uint32_t sbp = smem_u32(smem);
    const int t   = blockIdx.x;
    const int og  = blockIdx.y;
    const int tid = threadIdx.x;
    const int wid = tid >> 5;
    const int lane = tid & 31;

    const int m0 = (wid & 3) * 16;    // b-tile
    const int n0 = (wid >> 2) * 32;   // o-half within og

    const uint32_t a_lane = sbp + SMP_A
        + (uint32_t)(m0 + (lane & 7) + ((lane >> 3) & 1) * 8) * PSTRIDE
        + (uint32_t)((lane >> 4) * 16);
    const uint32_t b_lane = sbp + SMP_B
        + (uint32_t)(n0 + (lane & 7) + (lane >> 4) * 8) * PSTRIDE
        + (uint32_t)(((lane >> 3) & 1) * 16);

    float C[4][4];
    #pragma unroll
    for (int nt = 0; nt < 4; ++nt)
        #pragma unroll
        for (int i = 0; i < 4; ++i) C[nt][i] = 0.f;

    const size_t hbase = (size_t)(t + 1) * B_ * H_;

    for (int jc = 0; jc < 4; ++jc) {
        // ---- stage A: hs splits, rows b (hi) / b+64 (lo), 128 j ----
        #pragma unroll
        for (int i = tid; i < 4096; i += 256) {
            int b = i >> 6, jw = i & 63;
            size_t src = hbase + (size_t)b * H_ + jc * 128 + jw * 2;
            uint32_t vhi = *(const uint32_t*)(g_hshi + src);
            uint32_t vlo = *(const uint32_t*)(g_hslo + src);
            *(uint32_t*)(smem + SMP_A + b * PSTRIDE + jw * 4) = vhi;
            *(uint32_t*)(smem + SMP_A + (b + 64) * PSTRIDE + jw * 4) = vlo;
        }
        // ---- stage B: Wo^T splits, rows o (hi) / o+64 (lo) ----
        #pragma unroll
        for (int i = tid; i < 4096; i += 256) {
            int oo = i & 63, jw = i >> 6;
            float v0 = Wo[(jc * 128 + jw * 2) * O_ + og * 64 + oo];
            float v1 = Wo[(jc * 128 + jw * 2 + 1) * O_ + og * 64 + oo];
            __nv_bfloat16 h0b = __float2bfloat16(v0);
            __nv_bfloat16 h1b = __float2bfloat16(v1);
            __nv_bfloat16 l0b = __float2bfloat16(v0 - __bfloat162float(h0b));
            __nv_bfloat16 l1b = __float2bfloat16(v1 - __bfloat162float(h1b));
            uint32_t hp = (uint32_t)__bfloat16_as_ushort(h0b) | ((uint32_t)__bfloat16_as_ushort(h1b) << 16);
            uint32_t lp = (uint32_t)__bfloat16_as_ushort(l0b) | ((uint32_t)__bfloat16_as_ushort(l1b) << 16);
            *(uint32_t*)(smem + SMP_B + oo * PSTRIDE + jw * 4) = hp;
            *(uint32_t*)(smem + SMP_B + (oo + 64) * PSTRIDE + jw * 4) = lp;
        }
        __syncthreads();

        #pragma unroll
        for (int s = 0; s < 8; ++s) {
            const uint32_t koff = (uint32_t)(s * 32);
            uint32_t ah0, ah1, ah2, ah3, al0, al1, al2, al3;
            LDSM_X4(ah0, ah1, ah2, ah3, a_lane + koff);
            LDSM_X4(al0, al1, al2, al3, a_lane + 64u * PSTRIDE + koff);
            uint32_t bh0, bh1, bh2, bh3, bh4, bh5, bh6, bh7;
            LDSM_X4(bh0, bh1, bh2, bh3, b_lane + koff);
            LDSM_X4(bh4, bh5, bh6, bh7, b_lane + 16u * PSTRIDE + koff);
            uint32_t bl0, bl1, bl2, bl3, bl4, bl5, bl6, bl7;
            LDSM_X4(bl0, bl1, bl2, bl3, b_lane + 64u * PSTRIDE + koff);
            LDSM_X4(bl4, bl5, bl6, bl7, b_lane + 80u * PSTRIDE + koff);
            MMA_BF16(C[0], ah0, ah1, ah2, ah3, bh0, bh1);
            MMA_BF16(C[0], al0, al1, al2, al3, bh0, bh1);
            MMA_BF16(C[0], ah0, ah1, ah2, ah3, bl0, bl1);
            MMA_BF16(C[1], ah0, ah1, ah2, ah3, bh2, bh3);
            MMA_BF16(C[1], al0, al1, al2, al3, bh2, bh3);
            MMA_BF16(C[1], ah0, ah1, ah2, ah3, bl2, bl3);
            MMA_BF16(C[2], ah0, ah1, ah2, ah3, bh4, bh5);
            MMA_BF16(C[2], al0, al1, al2, al3, bh4, bh5);
            MMA_BF16(C[2], ah0, ah1, ah2, ah3, bl4, bl5);
            MMA_BF16(C[3], ah0, ah1, ah2, ah3, bh6, bh7);
            MMA_BF16(C[3], al0, al1, al2, al3, bh6, bh7);
            MMA_BF16(C[3], ah0, ah1, ah2, ah3, bl6, bl7);
        }
        __syncthreads();
    }

    // ---- epilogue: bias + store ----
    const int r0 = m0 + (lane >> 2);
    const int cbase = og * 64 + n0 + 2 * (lane & 3);
    #pragma unroll
    for (int nt = 0; nt < 4; ++nt) {
        int o = cbase + nt * 8;
        float2 bv = *(const float2*)(bo + o);
        *(float2*)(out + ((size_t)r0 * T_ + t) * O_ + o)
            = make_float2(C[nt][0] + bv.x, C[nt][1] + bv.y);
        *(float2*)(out + ((size_t)(r0 + 8) * T_ + t) * O_ + o)
            = make_float2(C[nt][2] + bv.x, C[nt][3] + bv.y);
    }
}

// ---------------- launch --------------------------------------------------
extern "C" void kernel_launch(void* const* d_in, const int* in_sizes, int n_in,
                              void* d_out, int out_size)
{
    const float* x   = (const float*)d_in[0];
    const float* h0  = (const float*)d_in[1];
    const float* c0  = (const float*)d_in[2];
    const float* W   = (const float*)d_in[3];
    const float* U   = (const float*)d_in[4];
    const float* bia = (const float*)d_in[5];
    const float* Wo  = (const float*)d_in[6];
    const float* bo  = (const float*)d_in[7];
    float* out = (float*)d_out;
    (void)in_sizes; (void)n_in; (void)out_size;

    cudaFuncSetAttribute(lstm_kernel,
                         cudaFuncAttributeMaxDynamicSharedMemorySize, SMEM_TOTAL);
    cudaFuncSetAttribute(proj_kernel,
                         cudaFuncAttributeMaxDynamicSharedMemorySize, SMEM_PROJ);

    prep_kernel<<<1024, 256>>>(x, h0);
    lstm_kernel<<<NCTA, NTHR, SMEM_TOTAL>>>(U, W, bia, c0);
    dim3 pg(T_, 4);
    proj_kernel<<<pg, 256, SMEM_PROJ>>>(Wo, bo, out);
}

// round 7
// speedup vs baseline: 3.5162x; 1.0154x over previous
#include <cuda_runtime.h>
#include <cuda_bf16.h>
#include <cstdint>

// Problem constants
#define B_  64
#define T_  512
#define D_  128
#define H_  512
#define O_  256

#define NCTA 128          // 4 batch-groups x 32 j-groups
#define NTHR 256          // 8 warps
#define KTOT 640

// ---------------- device scratch ------------------------------------------
__device__ __align__(128) uint16_t g_hshi[(T_ + 1) * B_ * H_];  // h history hi, [t][b][j]
__device__ __align__(128) uint16_t g_hslo[(T_ + 1) * B_ * H_];  // h history lo
__device__ __align__(128) uint16_t g_xhi[T_ * B_ * D_];         // x hi, [t][b][d]
__device__ __align__(128) uint16_t g_xlo[T_ * B_ * D_];
__device__ __align__(128) uint16_t g_woThi[O_ * H_];            // Wo^T hi, [o][j]
__device__ __align__(128) uint16_t g_woTlo[O_ * H_];
__device__ unsigned g_bar4[4];

// ---------------- PTX helpers ---------------------------------------------
__device__ __forceinline__ uint32_t smem_u32(const void* p) {
    uint32_t a;
    asm("{ .reg .u64 t; cvta.to.shared.u64 t, %1; cvt.u32.u64 %0, t; }" : "=r"(a) : "l"(p));
    return a;
}
__device__ __forceinline__ void cp16(uint32_t s, const void* g) {
    asm volatile("cp.async.cg.shared.global [%0], [%1], 16;" :: "r"(s), "l"(g));
}
#define CP_COMMIT() asm volatile("cp.async.commit_group;" ::: "memory")
#define CP_WAIT0()  asm volatile("cp.async.wait_group 0;" ::: "memory")

#define LDSM_X4(r0, r1, r2, r3, addr) \
    asm volatile("ldmatrix.sync.aligned.m8n8.x4.shared.b16 {%0,%1,%2,%3}, [%4];" \
        : "=r"(r0), "=r"(r1), "=r"(r2), "=r"(r3) : "r"(addr))

#define MMA_BF16(c, a0, a1, a2, a3, b0, b1) \
    asm volatile("mma.sync.aligned.m16n8k16.row.col.f32.bf16.bf16.f32 " \
        "{%0,%1,%2,%3}, {%4,%5,%6,%7}, {%8,%9}, {%0,%1,%2,%3};" \
        : "+f"((c)[0]), "+f"((c)[1]), "+f"((c)[2]), "+f"((c)[3]) \
        : "r"(a0), "r"(a1), "r"(a2), "r"(a3), "r"(b0), "r"(b1))

__device__ __forceinline__ float sig_f(float x) {
    return __fdividef(1.0f, 1.0f + __expf(-x));
}
__device__ __forceinline__ float tanh_f(float x) {
    return __fdividef(2.0f, 1.0f + __expf(-2.0f * x)) - 1.0f;
}

// ---------------- prep ----------------------------------------------------
__global__ void prep_kernel(const float* __restrict__ x, const float* __restrict__ h0,
                            const float* __restrict__ Wo)
{
    int stride = gridDim.x * blockDim.x;
    int tid0 = blockIdx.x * blockDim.x + threadIdx.x;
    if (tid0 < 4) g_bar4[tid0] = 0;
    for (int i = tid0; i < T_ * B_ * D_; i += stride) {
        int d = i & (D_ - 1);
        int b = (i >> 7) & (B_ - 1);
        int t = i >> 13;
        float v = x[(b * T_ + t) * D_ + d];
        __nv_bfloat16 hb = __float2bfloat16(v);
        __nv_bfloat16 lb = __float2bfloat16(v - __bfloat162float(hb));
        g_xhi[i] = __bfloat16_as_ushort(hb);
        g_xlo[i] = __bfloat16_as_ushort(lb);
    }
    for (int i = tid0; i < B_ * H_; i += stride) {
        float v = h0[i];
        __nv_bfloat16 hb = __float2bfloat16(v);
        __nv_bfloat16 lb = __float2bfloat16(v - __bfloat162float(hb));
        g_hshi[i] = __bfloat16_as_ushort(hb);
        g_hslo[i] = __bfloat16_as_ushort(lb);
    }
    // Wo^T bf16 splits: [o][j]
    for (int i = tid0; i < O_ * H_; i += stride) {
        int o = i >> 9, j = i & (H_ - 1);
        float v = Wo[j * O_ + o];
        __nv_bfloat16 hb = __float2bfloat16(v);
        __nv_bfloat16 lb = __float2bfloat16(v - __bfloat162float(hb));
        g_woThi[i] = __bfloat16_as_ushort(hb);
        g_woTlo[i] = __bfloat16_as_ushort(lb);
    }
}

// ---------------- lstm SMEM layout ----------------------------------------
// zp0-3:  4 x [16][68] f32                     = 17408 B   @ 0
// A-h  :  32 rows x 512 bf16, stride 1040 B    = 33280 B   @ 17408
// X    :  2 bufs x 32 rows x 128 bf16, str 272 = 17408 B   @ 50688
// Bbld :  64 rows x 640 bf16, stride 1296      = 82944 B   @ 68096 (init only;
//         reused as zp4-7 afterwards)
#define HSTR      1040
#define XSTR      272
#define XBUF      8704
#define BSTR      1296
#define ZSTR      68
#define ZPBUF     (16 * ZSTR)
#define SM_ZP     0
#define SM_A      17408
#define SM_X      50688
#define SM_BB     68096
#define SMEM_TOTAL (SM_BB + 64 * BSTR)         // 151040

__global__ void __launch_bounds__(NTHR, 1)
lstm_kernel(const float* __restrict__ U,    // [H][4H]
            const float* __restrict__ W,    // [D][4H]
            const float* __restrict__ bias, // [4H]
            const float* __restrict__ c0)   // [B][H]
{
    extern __shared__ char smem[];
    const uint32_t sb = smem_u32(smem);

    const int tid  = threadIdx.x;
    const int wid  = tid >> 5;
    const int lane = tid & 31;
    const int bg   = blockIdx.x & 3;
    const int jg   = blockIdx.x >> 2;

    // ---- per-thread persistent state ----
    const int tb = tid >> 4;
    const int tj = tid & 15;
    const int gb = bg * 16 + tb;
    const int gj = jg * 16 + tj;
    float c_st = c0[gb * H_ + gj];
    const float bi  = bias[gj];
    const float bf  = bias[H_ + gj];
    const float bgc = bias[2 * H_ + gj];
    const float bo_ = bias[3 * H_ + gj];

    // ---- B fragments: two-pass build (hi, then lo) + register hoist ----
    // warp w K-slices: h k=[64w,64w+64) (s=0..3), x k=[16w,16w+16) (s=4)
    const uint32_t b_lane = sb + SM_BB
        + (uint32_t)((lane & 7) + (lane >> 4) * 8) * BSTR
        + (uint32_t)(((lane >> 3) & 1) * 16);
    uint32_t Bh[5][4][4], Bl[5][4][4];
    #pragma unroll
    for (int pass = 0; pass < 2; ++pass) {
        __syncthreads();
        for (int n = 0; n < 64; ++n) {
            int col = (n & 3) * H_ + jg * 16 + (n >> 2);
            for (int k = tid; k < KTOT; k += NTHR) {
                float v = (k < H_) ? U[k * (4 * H_) + col] : W[(k - H_) * (4 * H_) + col];
                __nv_bfloat16 hb = __float2bfloat16(v);
                uint16_t outv = pass == 0
                    ? __bfloat16_as_ushort(hb)
                    : __bfloat16_as_ushort(__float2bfloat16(v - __bfloat162float(hb)));
                *(uint16_t*)(smem + SM_BB + n * BSTR + k * 2) = outv;
            }
        }
        __syncthreads();
        #pragma unroll
        for (int s = 0; s < 5; ++s) {
            uint32_t koff = (s < 4) ? (uint32_t)(128 * wid + 32 * s)
                                    : (uint32_t)(1024 + 32 * wid);
            #pragma unroll
            for (int g = 0; g < 4; ++g) {
                if (pass == 0) {
                    LDSM_X4(Bh[s][g][0], Bh[s][g][1], Bh[s][g][2], Bh[s][g][3],
                            b_lane + (uint32_t)(g * 16 * BSTR) + koff);
                } else {
                    LDSM_X4(Bl[s][g][0], Bl[s][g][1], Bl[s][g][2], Bl[s][g][3],
                            b_lane + (uint32_t)(g * 16 * BSTR) + koff);
                }
            }
        }
    }
    __syncthreads();   // B region now free for zp4-7

    // ---- stage x(0) into x-buffer 0 ----
    for (int i = tid; i < 512; i += NTHR) {
        int row = i >> 4, c = i & 15;
        uint32_t dst = sb + SM_X + row * XSTR + c * 16;
        const uint16_t* src = ((row < 16) ? g_xhi : g_xlo)
                            + (size_t)(bg * 16 + (row & 15)) * D_ + c * 8;
        cp16(dst, src);
    }
    CP_COMMIT();

    // ---- ldmatrix lane base addresses ----
    const uint32_t rowpat = (uint32_t)((lane & 7) + ((lane >> 3) & 1) * 8);
    const uint32_t a_lane = sb + SM_A + rowpat * HSTR + (uint32_t)((lane >> 4) * 16);
    const uint32_t x_lane = sb + SM_X + rowpat * XSTR + (uint32_t)((lane >> 4) * 16)
                          + (uint32_t)(32 * wid);
    const uint32_t kb_h = (uint32_t)(128 * wid);   // h-slice byte offset

    for (int t = 0; t < T_; ++t) {
        // ---- stage h(t): 32 rows x 64 chunks of 16B ----
        {
            const size_t hoff = (size_t)t * B_ * H_;
            #pragma unroll
            for (int i = tid; i < 2048; i += NTHR) {
                int row = i >> 6, c = i & 63;
                uint32_t dst = sb + SM_A + row * HSTR + c * 16;
                const uint16_t* src = ((row < 16) ? g_hshi : g_hslo)
                                    + hoff + (size_t)(bg * 16 + (row & 15)) * H_ + c * 8;
                cp16(dst, src);
            }
        }
        CP_COMMIT();
        CP_WAIT0();
        __syncthreads();                                  // [1]

        // ---- MMA: 5 k-steps (4 h + 1 x), 8 n-tiles, 3 split terms ----
        float C[8][4];
        #pragma unroll
        for (int nt = 0; nt < 8; ++nt)
            #pragma unroll
            for (int i = 0; i < 4; ++i) C[nt][i] = 0.f;

        const uint32_t xb = x_lane + (uint32_t)((t & 1) * XBUF);
        #pragma unroll
        for (int s = 0; s < 5; ++s) {
            uint32_t ah0, ah1, ah2, ah3, al0, al1, al2, al3;
            if (s < 4) {
                const uint32_t koff = kb_h + (uint32_t)(32 * s);
                LDSM_X4(ah0, ah1, ah2, ah3, a_lane + koff);
                LDSM_X4(al0, al1, al2, al3, a_lane + 16u * HSTR + koff);
            } else {
                LDSM_X4(ah0, ah1, ah2, ah3, xb);
                LDSM_X4(al0, al1, al2, al3, xb + 16u * XSTR);
            }
            #pragma unroll
            for (int g = 0; g < 4; ++g) {
                MMA_BF16(C[2 * g],     ah0, ah1, ah2, ah3, Bh[s][g][0], Bh[s][g][1]);
                MMA_BF16(C[2 * g],     al0, al1, al2, al3, Bh[s][g][0], Bh[s][g][1]);
                MMA_BF16(C[2 * g],     ah0, ah1, ah2, ah3, Bl[s][g][0], Bl[s][g][1]);
                MMA_BF16(C[2 * g + 1], ah0, ah1, ah2, ah3, Bh[s][g][2], Bh[s][g][3]);
                MMA_BF16(C[2 * g + 1], al0, al1, al2, al3, Bh[s][g][2], Bh[s][g][3]);
                MMA_BF16(C[2 * g + 1], ah0, ah1, ah2, ah3, Bl[s][g][2], Bl[s][g][3]);
            }
        }

        // ---- partial writes (own buffer, no sync needed) + x(t+1) prefetch ----
        {
            float* zb = (wid < 4)
                ? (float*)(smem + SM_ZP) + wid * ZPBUF
                : (float*)(smem + SM_BB) + (wid - 4) * ZPBUF;
            int r0 = lane >> 2;
            int cc = 2 * (lane & 3);
            #pragma unroll
            for (int nt = 0; nt < 8; ++nt) {
                int n0 = nt * 8 + cc;
                *(float2*)(zb + r0 * ZSTR + n0)       = make_float2(C[nt][0], C[nt][1]);
                *(float2*)(zb + (r0 + 8) * ZSTR + n0) = make_float2(C[nt][2], C[nt][3]);
            }
        }
        if (t + 1 < T_) {
            const size_t xoff = (size_t)(t + 1) * B_ * D_;
            const uint32_t xdstb = sb + SM_X + (uint32_t)(((t + 1) & 1) * XBUF);
            #pragma unroll
            for (int i = tid; i < 512; i += NTHR) {
                int row = i >> 4, c = i & 15;
                uint32_t dst = xdstb + row * XSTR + c * 16;
                const uint16_t* src = ((row < 16) ? g_xhi : g_xlo)
                                    + xoff + (size_t)(bg * 16 + (row & 15)) * D_ + c * 8;
                cp16(dst, src);
            }
        }
        CP_COMMIT();
        __syncthreads();                                  // [2]

        // ---- gates: one thread per (b, j); sum 8 partial buffers ----
        {
            float zi = bi, zf = bf, zg = bgc, zo = bo_;
            #pragma unroll
            for (int q = 0; q < 8; ++q) {
                const float* zb = (q < 4)
                    ? (const float*)(smem + SM_ZP) + q * ZPBUF
                    : (const float*)(smem + SM_BB) + (q - 4) * ZPBUF;
                float4 v = *(const float4*)(zb + tb * ZSTR + tj * 4);
                zi += v.x; zf += v.y; zg += v.z; zo += v.w;
            }
            float ig = sig_f(zi);
            float fg = sig_f(zf);
            float gg = tanh_f(zg);
            float og = sig_f(zo);
            float cn = fg * c_st + ig * gg;
            c_st = cn;
            float hn = og * tanh_f(cn);
            __nv_bfloat16 hb = __float2bfloat16(hn);
            __nv_bfloat16 lb = __float2bfloat16(hn - __bfloat162float(hb));
            size_t idx = ((size_t)(t + 1) * B_ + gb) * H_ + gj;
            g_hshi[idx] = __bfloat16_as_ushort(hb);
            g_hslo[idx] = __bfloat16_as_ushort(lb);
        }

        // ---- per-batch-group barrier (32 CTAs) ----
        __syncthreads();                                  // [3]
        if (tid == 0) {
            __threadfence();
            atomicAdd(&g_bar4[bg], 1u);
            unsigned target = 32u * (unsigned)(t + 1);
            while (*(volatile unsigned*)&g_bar4[bg] < target) { }
            __threadfence();
        }
        __syncthreads();                                  // [4]
    }
}

// ---------------- HMMA output projection ----------------------------------
#define PSTRIDE 272
#define SMP_A   0
#define SMP_B   (128 * PSTRIDE)
#define SMEM_PROJ (SMP_B + 128 * PSTRIDE)       // 69632

__global__ void __launch_bounds__(256) proj_kernel(
    const float* __restrict__ bo,   // [O]
    float* __restrict__ out)        // [B][T][O]
{
    extern __shared__ char smem[];
    const uint32_t sbp = smem_u32(smem);
    const int t   = blockIdx.x;
    const int og  = blockIdx.y;
    const int tid = threadIdx.x;
    const int wid = tid >> 5;
    const int lane = tid & 31;

    const int m0 = (wid & 3) * 16;
    const int n0 = (wid >> 2) * 32;

    const uint32_t a_lane = sbp + SMP_A
        + (uint32_t)(m0 + (lane & 7) + ((lane >> 3) & 1) * 8) * PSTRIDE
        + (uint32_t)((lane >> 4) * 16);
    const uint32_t b_lane = sbp + SMP_B
        + (uint32_t)(n0 + (lane & 7) + (lane >> 4) * 8) * PSTRIDE
        + (uint32_t)(((lane >> 3) & 1) * 16);

    float C[4][4];
    #pragma unroll
    for (int nt = 0; nt < 4; ++nt)
        #pragma unroll
        for (int i = 0; i < 4; ++i) C[nt][i] = 0.f;

    const size_t hbase = (size_t)(t + 1) * B_ * H_;

    for (int jc = 0; jc < 4; ++jc) {
        // A: hs splits (rows b hi / b+64 lo), 128 j per chunk; 16B cp.async
        #pragma unroll
        for (int i = tid; i < 2048; i += 256) {
            int row = i >> 4, c = i & 15;
            uint32_t dst = sbp + SMP_A + row * PSTRIDE + c * 16;
            const uint16_t* src = ((row < 64) ? g_hshi : g_hslo)
                                + hbase + (size_t)(row & 63) * H_ + jc * 128 + c * 8;
            cp16(dst, src);
        }
        // B: Wo^T splits (rows o hi / o+64 lo)
        #pragma unroll
        for (int i = tid; i < 2048; i += 256) {
            int row = i >> 4, c = i & 15;
            uint32_t dst = sbp + SMP_B + row * PSTRIDE + c * 16;
            const uint16_t* src = ((row < 64) ? g_woThi : g_woTlo)
                                + (size_t)(og * 64 + (row & 63)) * H_ + jc * 128 + c * 8;
            cp16(dst, src);
        }
        CP_COMMIT();
        CP_WAIT0();
        __syncthreads();

        #pragma unroll
        for (int s = 0; s < 8; ++s) {
            const uint32_t koff = (uint32_t)(s * 32);
            uint32_t ah0, ah1, ah2, ah3, al0, al1, al2, al3;
            LDSM_X4(ah0, ah1, ah2, ah3, a_lane + koff);
            LDSM_X4(al0, al1, al2, al3, a_lane + 64u * PSTRIDE + koff);
            uint32_t bh0, bh1, bh2, bh3, bh4, bh5, bh6, bh7;
            LDSM_X4(bh0, bh1, bh2, bh3, b_lane + koff);
            LDSM_X4(bh4, bh5, bh6, bh7, b_lane + 16u * PSTRIDE + koff);
            uint32_t bl0, bl1, bl2, bl3, bl4, bl5, bl6, bl7;
            LDSM_X4(bl0, bl1, bl2, bl3, b_lane + 64u * PSTRIDE + koff);
            LDSM_X4(bl4, bl5, bl6, bl7, b_lane + 80u * PSTRIDE + koff);
            MMA_BF16(C[0], ah0, ah1, ah2, ah3, bh0, bh1);
            MMA_BF16(C[0], al0, al1, al2, al3, bh0, bh1);
            MMA_BF16(C[0], ah0, ah1, ah2, ah3, bl0, bl1);
            MMA_BF16(C[1], ah0, ah1, ah2, ah3, bh2, bh3);
            MMA_BF16(C[1], al0, al1, al2, al3, bh2, bh3);
            MMA_BF16(C[1], ah0, ah1, ah2, ah3, bl2, bl3);
            MMA_BF16(C[2], ah0, ah1, ah2, ah3, bh4, bh5);
            MMA_BF16(C[2], al0, al1, al2, al3, bh4, bh5);
            MMA_BF16(C[2], ah0, ah1, ah2, ah3, bl4, bl5);
            MMA_BF16(C[3], ah0, ah1, ah2, ah3, bh6, bh7);
            MMA_BF16(C[3], al0, al1, al2, al3, bh6, bh7);
            MMA_BF16(C[3], ah0, ah1, ah2, ah3, bl6, bl7);
        }
        __syncthreads();
    }

    const int r0 = m0 + (lane >> 2);
    const int cbase = og * 64 + n0 + 2 * (lane & 3);
    #pragma unroll
    for (int nt = 0; nt < 4; ++nt) {
        int o = cbase + nt * 8;
        float2 bv = *(const float2*)(bo + o);
        *(float2*)(out + ((size_t)r0 * T_ + t) * O_ + o)
            = make_float2(C[nt][0] + bv.x, C[nt][1] + bv.y);
        *(float2*)(out + ((size_t)(r0 + 8) * T_ + t) * O_ + o)
            = make_float2(C[nt][2] + bv.x, C[nt][3] + bv.y);
    }
}

// ---------------- launch --------------------------------------------------
extern "C" void kernel_launch(void* const* d_in, const int* in_sizes, int n_in,
                              void* d_out, int out_size)
{
    const float* x   = (const float*)d_in[0];
    const float* h0  = (const float*)d_in[1];
    const float* c0  = (const float*)d_in[2];
    const float* W   = (const float*)d_in[3];
    const float* U   = (const float*)d_in[4];
    const float* bia = (const float*)d_in[5];
    const float* Wo  = (const float*)d_in[6];
    const float* bo  = (const float*)d_in[7];
    float* out = (float*)d_out;
    (void)in_sizes; (void)n_in; (void)out_size;

    cudaFuncSetAttribute(lstm_kernel,
                         cudaFuncAttributeMaxDynamicSharedMemorySize, SMEM_TOTAL);
    cudaFuncSetAttribute(proj_kernel,
                         cudaFuncAttributeMaxDynamicSharedMemorySize, SMEM_PROJ);

    prep_kernel<<<1024, 256>>>(x, h0, Wo);
    lstm_kernel<<<NCTA, NTHR, SMEM_TOTAL>>>(U, W, bia, c0);
    dim3 pg(T_, 4);
    proj_kernel<<<pg, 256, SMEM_PROJ>>>(bo, out);
}

// round 8
// speedup vs baseline: 3.6219x; 1.0301x over previous
#include <cuda_runtime.h>
#include <cuda_bf16.h>
#include <cstdint>

// Problem constants
#define B_  64
#define T_  512
#define D_  128
#define H_  512
#define O_  256

#define NCTA 128          // 4 batch-groups x 32 j-groups
#define NTHR 256          // 8 warps
#define KTOT 640

// ---------------- device scratch ------------------------------------------
__device__ __align__(128) uint16_t g_hshi[(T_ + 1) * B_ * H_];  // h history hi, [t][b][j]
__device__ __align__(128) uint16_t g_hslo[(T_ + 1) * B_ * H_];  // h history lo
__device__ __align__(128) uint16_t g_xhi[T_ * B_ * D_];         // x hi, [t][b][d]
__device__ __align__(128) uint16_t g_xlo[T_ * B_ * D_];
__device__ __align__(128) uint16_t g_woThi[O_ * H_];            // Wo^T hi, [o][j]
__device__ __align__(128) uint16_t g_woTlo[O_ * H_];
__device__ __align__(128) unsigned g_flags[4][32];              // per-(bg, jg) step flags

// ---------------- PTX helpers ---------------------------------------------
__device__ __forceinline__ uint32_t smem_u32(const void* p) {
    uint32_t a;
    asm("{ .reg .u64 t; cvta.to.shared.u64 t, %1; cvt.u32.u64 %0, t; }" : "=r"(a) : "l"(p));
    return a;
}
__device__ __forceinline__ void cp16(uint32_t s, const void* g) {
    asm volatile("cp.async.cg.shared.global [%0], [%1], 16;" :: "r"(s), "l"(g));
}
#define CP_COMMIT() asm volatile("cp.async.commit_group;" ::: "memory")
#define CP_WAIT0()  asm volatile("cp.async.wait_group 0;" ::: "memory")

#define LDSM_X4(r0, r1, r2, r3, addr) \
    asm volatile("ldmatrix.sync.aligned.m8n8.x4.shared.b16 {%0,%1,%2,%3}, [%4];" \
        : "=r"(r0), "=r"(r1), "=r"(r2), "=r"(r3) : "r"(addr))

#define MMA_BF16(c, a0, a1, a2, a3, b0, b1) \
    asm volatile("mma.sync.aligned.m16n8k16.row.col.f32.bf16.bf16.f32 " \
        "{%0,%1,%2,%3}, {%4,%5,%6,%7}, {%8,%9}, {%0,%1,%2,%3};" \
        : "+f"((c)[0]), "+f"((c)[1]), "+f"((c)[2]), "+f"((c)[3]) \
        : "r"(a0), "r"(a1), "r"(a2), "r"(a3), "r"(b0), "r"(b1))

__device__ __forceinline__ uint32_t ldcg32(const uint16_t* p) {
    uint32_t v;
    asm volatile("ld.global.cg.u32 %0, [%1];" : "=r"(v) : "l"(p));
    return v;
}

__device__ __forceinline__ float sig_f(float x) {
    return __fdividef(1.0f, 1.0f + __expf(-x));
}
__device__ __forceinline__ float tanh_f(float x) {
    return __fdividef(2.0f, 1.0f + __expf(-2.0f * x)) - 1.0f;
}

// ---------------- prep ----------------------------------------------------
__global__ void prep_kernel(const float* __restrict__ x, const float* __restrict__ h0,
                            const float* __restrict__ Wo)
{
    int stride = gridDim.x * blockDim.x;
    int tid0 = blockIdx.x * blockDim.x + threadIdx.x;
    if (tid0 < 128) ((unsigned*)g_flags)[tid0] = 0;
    for (int i = tid0; i < T_ * B_ * D_; i += stride) {
        int d = i & (D_ - 1);
        int b = (i >> 7) & (B_ - 1);
        int t = i >> 13;
        float v = x[(b * T_ + t) * D_ + d];
        __nv_bfloat16 hb = __float2bfloat16(v);
        __nv_bfloat16 lb = __float2bfloat16(v - __bfloat162float(hb));
        g_xhi[i] = __bfloat16_as_ushort(hb);
        g_xlo[i] = __bfloat16_as_ushort(lb);
    }
    for (int i = tid0; i < B_ * H_; i += stride) {
        float v = h0[i];
        __nv_bfloat16 hb = __float2bfloat16(v);
        __nv_bfloat16 lb = __float2bfloat16(v - __bfloat162float(hb));
        g_hshi[i] = __bfloat16_as_ushort(hb);
        g_hslo[i] = __bfloat16_as_ushort(lb);
    }
    for (int i = tid0; i < O_ * H_; i += stride) {
        int o = i >> 9, j = i & (H_ - 1);
        float v = Wo[j * O_ + o];
        __nv_bfloat16 hb = __float2bfloat16(v);
        __nv_bfloat16 lb = __float2bfloat16(v - __bfloat162float(hb));
        g_woThi[i] = __bfloat16_as_ushort(hb);
        g_woTlo[i] = __bfloat16_as_ushort(lb);
    }
}

// ---------------- lstm SMEM layout ----------------------------------------
// zp0-3 : 4 x [16][68] f32 = 17408 B @ 0
// zp4-7 : 4 x [16][68] f32 = 17408 B @ 17408
// B     : 64 rows x 640 bf16, stride 1296 B = 82944 B @ 34816 (persistent)
#define BSTR      1296
#define ZSTR      68
#define ZPBUF     (16 * ZSTR)
#define SM_ZP     0
#define SM_ZP2    17408
#define SM_BB     34816
#define SMEM_TOTAL (SM_BB + 64 * BSTR)         // 117760

__global__ void __launch_bounds__(NTHR, 1)
lstm_kernel(const float* __restrict__ U,    // [H][4H]
            const float* __restrict__ W,    // [D][4H]
            const float* __restrict__ bias, // [4H]
            const float* __restrict__ c0)   // [B][H]
{
    extern __shared__ char smem[];
    const uint32_t sb = smem_u32(smem);

    const int tid  = threadIdx.x;
    const int wid  = tid >> 5;
    const int lane = tid & 31;
    const int bg   = blockIdx.x & 3;
    const int jg   = blockIdx.x >> 2;

    // ---- per-thread persistent state ----
    const int tb = tid >> 4;
    const int tj = tid & 15;
    const int gb = bg * 16 + tb;
    const int gj = jg * 16 + tj;
    float c_st = c0[gb * H_ + gj];
    const float bi  = bias[gj];
    const float bf  = bias[H_ + gj];
    const float bgc = bias[2 * H_ + gj];
    const float bo_ = bias[3 * H_ + gj];

    // ---- B fragments: two-pass build (hi, then lo); h-slices (s=0..3) hoisted
    //      to registers, x-slice (s=4) stays in persistent smem ----
    const uint32_t b_lane = sb + SM_BB
        + (uint32_t)((lane & 7) + (lane >> 4) * 8) * BSTR
        + (uint32_t)(((lane >> 3) & 1) * 16);
    uint32_t Bh[4][4][4], Bl[4][4][4];
    #pragma unroll
    for (int pass = 0; pass < 2; ++pass) {
        // pass 0: rows hold hi weights -> hoist h-slices; then rows k<H flip to lo.
        for (int n = 0; n < 64; ++n) {
            int col = (n & 3) * H_ + jg * 16 + (n >> 2);
            for (int k = tid; k < KTOT; k += NTHR) {
                if (pass == 1 && k >= H_) continue;   // keep x-lo? no: see below
                float v = (k < H_) ? U[k * (4 * H_) + col] : W[(k - H_) * (4 * H_) + col];
                __nv_bfloat16 hb = __float2bfloat16(v);
                uint16_t outv = (pass == 0)
                    ? __bfloat16_as_ushort(hb)
                    : __bfloat16_as_ushort(__float2bfloat16(v - __bfloat162float(hb)));
                *(uint16_t*)(smem + SM_BB + n * BSTR + k * 2) = outv;
            }
        }
        __syncthreads();
        #pragma unroll
        for (int s = 0; s < 4; ++s) {
            uint32_t koff = (uint32_t)(128 * wid + 32 * s);
            #pragma unroll
            for (int g = 0; g < 4; ++g) {
                if (pass == 0) {
                    LDSM_X4(Bh[s][g][0], Bh[s][g][1], Bh[s][g][2], Bh[s][g][3],
                            b_lane + (uint32_t)(g * 16 * BSTR) + koff);
                } else {
                    LDSM_X4(Bl[s][g][0], Bl[s][g][1], Bl[s][g][2], Bl[s][g][3],
                            b_lane + (uint32_t)(g * 16 * BSTR) + koff);
                }
            }
        }
        __syncthreads();
    }
    // After pass 1: smem B rows k<H hold lo; k>=H still hold HI (x-hi).
    // Rebuild x columns as: hi in [1024,1280) stays; store x-LO at a second
    // region? Instead: overwrite k>=H with LO now and ldmatrix x-hi fragments
    // BEFORE that. Simpler: hoist x-hi B-frags to registers now (16 regs),
    // then overwrite x rows with lo (persistent smem holds x-lo only).
    uint32_t Bxh[4][4];
    {
        uint32_t koff = (uint32_t)(1024 + 32 * wid);
        #pragma unroll
        for (int g = 0; g < 4; ++g)
            LDSM_X4(Bxh[g][0], Bxh[g][1], Bxh[g][2], Bxh[g][3],
                    b_lane + (uint32_t)(g * 16 * BSTR) + koff);
    }
    __syncthreads();
    for (int n = 0; n < 64; ++n) {
        int col = (n & 3) * H_ + jg * 16 + (n >> 2);
        for (int k = H_ + tid; k < KTOT; k += NTHR) {
            float v = W[(k - H_) * (4 * H_) + col];
            __nv_bfloat16 hb = __float2bfloat16(v);
            *(uint16_t*)(smem + SM_BB + n * BSTR + k * 2) =
                __bfloat16_as_ushort(__float2bfloat16(v - __bfloat162float(hb)));
        }
    }
    __syncthreads();
    uint32_t Bxl[4][4];
    {
        uint32_t koff = (uint32_t)(1024 + 32 * wid);
        #pragma unroll
        for (int g = 0; g < 4; ++g)
            LDSM_X4(Bxl[g][0], Bxl[g][1], Bxl[g][2], Bxl[g][3],
                    b_lane + (uint32_t)(g * 16 * BSTR) + koff);
    }
    __syncthreads();   // B smem region now free -> zp4-7 lives at SM_ZP2 anyway

    // ---- fragment-row constants ----
    const int fr  = lane >> 2;           // 0..7
    const int cq  = (lane & 3) * 2;      // 0,2,4,6
    const int fb0 = bg * 16 + fr;        // A rows (batches)
    const int fb1 = fb0 + 8;
    const int jb  = 64 * wid + cq;       // h k-slice base (j index)
    const int db  = 16 * wid + cq;       // x k-slice base (d index)

    for (int t = 0; t < T_; ++t) {
        float C[8][4];
        #pragma unroll
        for (int nt = 0; nt < 8; ++nt)
            #pragma unroll
            for (int i = 0; i < 4; ++i) C[nt][i] = 0.f;

        // ---- x phase (independent of h(t)) : direct-LDG A frags + MMA ----
        {
            const size_t xo = (size_t)t * (B_ * D_);
            const uint16_t* xh0 = g_xhi + xo + (size_t)fb0 * D_;
            const uint16_t* xh1 = g_xhi + xo + (size_t)fb1 * D_;
            const uint16_t* xl0 = g_xlo + xo + (size_t)fb0 * D_;
            const uint16_t* xl1 = g_xlo + xo + (size_t)fb1 * D_;
            uint32_t a0 = ldcg32(xh0 + db), a1 = ldcg32(xh1 + db);
            uint32_t a2 = ldcg32(xh0 + db + 8), a3 = ldcg32(xh1 + db + 8);
            uint32_t l0 = ldcg32(xl0 + db), l1 = ldcg32(xl1 + db);
            uint32_t l2 = ldcg32(xl0 + db + 8), l3 = ldcg32(xl1 + db + 8);
            #pragma unroll
            for (int g = 0; g < 4; ++g) {
                MMA_BF16(C[2 * g],     a0, a1, a2, a3, Bxh[g][0], Bxh[g][1]);
                MMA_BF16(C[2 * g],     l0, l1, l2, l3, Bxh[g][0], Bxh[g][1]);
                MMA_BF16(C[2 * g],     a0, a1, a2, a3, Bxl[g][0], Bxl[g][1]);
                MMA_BF16(C[2 * g + 1], a0, a1, a2, a3, Bxh[g][2], Bxh[g][3]);
                MMA_BF16(C[2 * g + 1], l0, l1, l2, l3, Bxh[g][2], Bxh[g][3]);
                MMA_BF16(C[2 * g + 1], a0, a1, a2, a3, Bxl[g][2], Bxl[g][3]);
            }
        }

        // ---- wait for h(t): lane-per-slot flag poll (warp 0) ----
        if (wid == 0 && t > 0) {
            const volatile unsigned* fl = (const volatile unsigned*)g_flags[bg];
            unsigned tgt = (unsigned)t;
            while (!__all_sync(0xFFFFFFFFu, fl[lane] >= tgt)) { }
        }
        __syncthreads();                                  // [A]

        // ---- h phase: direct-LDG A frags (L1-bypassing), then MMAs ----
        {
            const size_t ho = (size_t)t * (B_ * H_);
            const uint16_t* hh0 = g_hshi + ho + (size_t)fb0 * H_;
            const uint16_t* hh1 = g_hshi + ho + (size_t)fb1 * H_;
            const uint16_t* hl0 = g_hslo + ho + (size_t)fb0 * H_;
            const uint16_t* hl1 = g_hslo + ho + (size_t)fb1 * H_;
            uint32_t ah[4][4], al[4][4];
            #pragma unroll
            for (int s = 0; s < 4; ++s) {
                int j0 = jb + 16 * s;
                ah[s][0] = ldcg32(hh0 + j0);     ah[s][1] = ldcg32(hh1 + j0);
                ah[s][2] = ldcg32(hh0 + j0 + 8); ah[s][3] = ldcg32(hh1 + j0 + 8);
                al[s][0] = ldcg32(hl0 + j0);     al[s][1] = ldcg32(hl1 + j0);
                al[s][2] = ldcg32(hl0 + j0 + 8); al[s][3] = ldcg32(hl1 + j0 + 8);
            }
            #pragma unroll
            for (int s = 0; s < 4; ++s) {
                #pragma unroll
                for (int g = 0; g < 4; ++g) {
                    MMA_BF16(C[2 * g],     ah[s][0], ah[s][1], ah[s][2], ah[s][3], Bh[s][g][0], Bh[s][g][1]);
                    MMA_BF16(C[2 * g],     al[s][0], al[s][1], al[s][2], al[s][3], Bh[s][g][0], Bh[s][g][1]);
                    MMA_BF16(C[2 * g],     ah[s][0], ah[s][1], ah[s][2], ah[s][3], Bl[s][g][0], Bl[s][g][1]);
                    MMA_BF16(C[2 * g + 1], ah[s][0], ah[s][1], ah[s][2], ah[s][3], Bh[s][g][2], Bh[s][g][3]);
                    MMA_BF16(C[2 * g + 1], al[s][0], al[s][1], al[s][2], al[s][3], Bh[s][g][2], Bh[s][g][3]);
                    MMA_BF16(C[2 * g + 1], ah[s][0], ah[s][1], ah[s][2], ah[s][3], Bl[s][g][2], Bl[s][g][3]);
                }
            }
        }

        // ---- write K-partials to own buffer ----
        {
            float* zb = (wid < 4)
                ? (float*)(smem + SM_ZP)  + wid * ZPBUF
                : (float*)(smem + SM_ZP2) + (wid - 4) * ZPBUF;
            int r0 = lane >> 2;
            int cc = 2 * (lane & 3);
            #pragma unroll
            for (int nt = 0; nt < 8; ++nt) {
                int n0 = nt * 8 + cc;
                *(float2*)(zb + r0 * ZSTR + n0)       = make_float2(C[nt][0], C[nt][1]);
                *(float2*)(zb + (r0 + 8) * ZSTR + n0) = make_float2(C[nt][2], C[nt][3]);
            }
        }
        __syncthreads();                                  // [B]

        // ---- gates: one thread per (b, j); sum 8 partial buffers ----
        {
            float zi = bi, zf = bf, zg = bgc, zo = bo_;
            #pragma unroll
            for (int q = 0; q < 8; ++q) {
                const float* zb = (q < 4)
                    ? (const float*)(smem + SM_ZP)  + q * ZPBUF
                    : (const float*)(smem + SM_ZP2) + (q - 4) * ZPBUF;
                float4 v = *(const float4*)(zb + tb * ZSTR + tj * 4);
                zi += v.x; zf += v.y; zg += v.z; zo += v.w;
            }
            float ig = sig_f(zi);
            float fg = sig_f(zf);
            float gg = tanh_f(zg);
            float og = sig_f(zo);
            float cn = fg * c_st + ig * gg;
            c_st = cn;
            float hn = og * tanh_f(cn);
            __nv_bfloat16 hb = __float2bfloat16(hn);
            __nv_bfloat16 lb = __float2bfloat16(hn - __bfloat162float(hb));
            size_t idx = ((size_t)(t + 1) * B_ + gb) * H_ + gj;
            g_hshi[idx] = __bfloat16_as_ushort(hb);
            g_hslo[idx] = __bfloat16_as_ushort(lb);
        }

        // ---- signal: own flag slot (no atomic contention) ----
        __syncthreads();                                  // [C]
        if (tid == 0) {
            __threadfence();
            *(volatile unsigned*)&g_flags[bg][jg] = (unsigned)(t + 1);
        }
    }
}

// ---------------- HMMA output projection ----------------------------------
#define PSTRIDE 272
#define SMP_A   0
#define SMP_B   (128 * PSTRIDE)
#define SMEM_PROJ (SMP_B + 128 * PSTRIDE)       // 69632

__global__ void __launch_bounds__(256) proj_kernel(
    const float* __restrict__ bo,   // [O]
    float* __restrict__ out)        // [B][T][O]
{
    extern __shared__ char smem[];
    const uint32_t sbp = smem_u32(smem);
    const int t   = blockIdx.x;
    const int og  = blockIdx.y;
    const int tid = threadIdx.x;
    const int wid = tid >> 5;
    const int lane = tid & 31;

    const int m0 = (wid & 3) * 16;
    const int n0 = (wid >> 2) * 32;

    const uint32_t a_lane = sbp + SMP_A
        + (uint32_t)(m0 + (lane & 7) + ((lane >> 3) & 1) * 8) * PSTRIDE
        + (uint32_t)((lane >> 4) * 16);
    const uint32_t b_lane = sbp + SMP_B
        + (uint32_t)(n0 + (lane & 7) + (lane >> 4) * 8) * PSTRIDE
        + (uint32_t)(((lane >> 3) & 1) * 16);

    float C[4][4];
    #pragma unroll
    for (int nt = 0; nt < 4; ++nt)
        #pragma unroll
        for (int i = 0; i < 4; ++i) C[nt][i] = 0.f;

    const size_t hbase = (size_t)(t + 1) * B_ * H_;

    for (int jc = 0; jc < 4; ++jc) {
        #pragma unroll
        for (int i = tid; i < 2048; i += 256) {
            int row = i >> 4, c = i & 15;
            uint32_t dst = sbp + SMP_A + row * PSTRIDE + c * 16;
            const uint16_t* src = ((row < 64) ? g_hshi : g_hslo)
                                + hbase + (size_t)(row & 63) * H_ + jc * 128 + c * 8;
            cp16(dst, src);
        }
        #pragma unroll
        for (int i = tid; i < 2048; i += 256) {
            int row = i >> 4, c = i & 15;
            uint32_t dst = sbp + SMP_B + row * PSTRIDE + c * 16;
            const uint16_t* src = ((row < 64) ? g_woThi : g_woTlo)
                                + (size_t)(og * 64 + (row & 63)) * H_ + jc * 128 + c * 8;
            cp16(dst, src);
        }
        CP_COMMIT();
        CP_WAIT0();
        __syncthreads();

        #pragma unroll
        for (int s = 0; s < 8; ++s) {
            const uint32_t koff = (uint32_t)(s * 32);
            uint32_t ah0, ah1, ah2, ah3, al0, al1, al2, al3;
            LDSM_X4(ah0, ah1, ah2, ah3, a_lane + koff);
            LDSM_X4(al0, al1, al2, al3, a_lane + 64u * PSTRIDE + koff);
            uint32_t bh0, bh1, bh2, bh3, bh4, bh5, bh6, bh7;
            LDSM_X4(bh0, bh1, bh2, bh3, b_lane + koff);
            LDSM_X4(bh4, bh5, bh6, bh7, b_lane + 16u * PSTRIDE + koff);
            uint32_t bl0, bl1, bl2, bl3, bl4, bl5, bl6, bl7;
            LDSM_X4(bl0, bl1, bl2, bl3, b_lane + 64u * PSTRIDE + koff);
            LDSM_X4(bl4, bl5, bl6, bl7, b_lane + 80u * PSTRIDE + koff);
            MMA_BF16(C[0], ah0, ah1, ah2, ah3, bh0, bh1);
            MMA_BF16(C[0], al0, al1, al2, al3, bh0, bh1);
            MMA_BF16(C[0], ah0, ah1, ah2, ah3, bl0, bl1);
            MMA_BF16(C[1], ah0, ah1, ah2, ah3, bh2, bh3);
            MMA_BF16(C[1], al0, al1, al2, al3, bh2, bh3);
            MMA_BF16(C[1], ah0, ah1, ah2, ah3, bl2, bl3);
            MMA_BF16(C[2], ah0, ah1, ah2, ah3, bh4, bh5);
            MMA_BF16(C[2], al0, al1, al2, al3, bh4, bh5);
            MMA_BF16(C[2], ah0, ah1, ah2, ah3, bl4, bl5);
            MMA_BF16(C[3], ah0, ah1, ah2, ah3, bh6, bh7);
            MMA_BF16(C[3], al0, al1, al2, al3, bh6, bh7);
            MMA_BF16(C[3], ah0, ah1, ah2, ah3, bl6, bl7);
        }
        __syncthreads();
    }

    const int r0 = m0 + (lane >> 2);
    const int cbase = og * 64 + n0 + 2 * (lane & 3);
    #pragma unroll
    for (int nt = 0; nt < 4; ++nt) {
        int o = cbase + nt * 8;
        float2 bv = *(const float2*)(bo + o);
        *(float2*)(out + ((size_t)r0 * T_ + t) * O_ + o)
            = make_float2(C[nt][0] + bv.x, C[nt][1] + bv.y);
        *(float2*)(out + ((size_t)(r0 + 8) * T_ + t) * O_ + o)
            = make_float2(C[nt][2] + bv.x, C[nt][3] + bv.y);
    }
}

// ---------------- launch --------------------------------------------------
extern "C" void kernel_launch(void* const* d_in, const int* in_sizes, int n_in,
                              void* d_out, int out_size)
{
    const float* x   = (const float*)d_in[0];
    const float* h0  = (const float*)d_in[1];
    const float* c0  = (const float*)d_in[2];
    const float* W   = (const float*)d_in[3];
    const float* U   = (const float*)d_in[4];
    const float* bia = (const float*)d_in[5];
    const float* Wo  = (const float*)d_in[6];
    const float* bo  = (const float*)d_in[7];
    float* out = (float*)d_out;
    (void)in_sizes; (void)n_in; (void)out_size;

    cudaFuncSetAttribute(lstm_kernel,
                         cudaFuncAttributeMaxDynamicSharedMemorySize, SMEM_TOTAL);
    cudaFuncSetAttribute(proj_kernel,
                         cudaFuncAttributeMaxDynamicSharedMemorySize, SMEM_PROJ);

    prep_kernel<<<1024, 256>>>(x, h0, Wo);
    lstm_kernel<<<NCTA, NTHR, SMEM_TOTAL>>>(U, W, bia, c0);
    dim3 pg(T_, 4);
    proj_kernel<<<pg, 256, SMEM_PROJ>>>(bo, out);
}